// round 8
// baseline (speedup 1.0000x reference)
#include <cuda_runtime.h>
#include <math.h>

namespace {
constexpr int    Bn = 32, Cn = 32, Ln = 16384, WIN = 64, HOP = 32;
constexpr int    NF = 511, ND = 33;
constexpr double PEN = 5.0;
constexpr int    MAXSEG = 520, MAXTOK = 4608, ANCH = 16;
constexpr double PI_D = 3.14159265358979323846264338327950288;
constexpr int    SEGBUF = 1024;
constexpr int    MTMAX = 2600;   // hard bound: <=2559 tokens/batch possible
}

// ------------------------------- scratch ----------------------------------
__device__ float  g_x[Bn][Cn][Ln];                    // staged input (HBM)
__device__ float  g_out[16640LL * MTMAX + 64];        // staged output (HBM)
__device__ float  g_sig[Bn][Ln];
__device__ double g_feats[Bn][NF][ND];
__device__ double g_cs [Bn][NF + 1][ND];
__device__ double g_cs2[Bn][NF + 1][ND];
__device__ int    g_nseg[Bn];
__device__ int    g_seg_s[Bn][MAXSEG];
__device__ int    g_seg_e[Bn][MAXSEG];
__device__ int    g_seg_off[Bn][MAXSEG];
__device__ double g_spec[Bn][Ln / 2 + 8];
__device__ double g_dp[Bn][MAXSEG];
__device__ double g_bwv[Bn][MAXSEG];
__device__ int    g_pl[Bn][MAXSEG];
__device__ int    g_ntok[Bn];
__device__ int    g_tok_s[Bn][MAXTOK];
__device__ int    g_tok_e[Bn][MAXTOK];
__device__ int    g_tok_seg[Bn][MAXTOK];

// precomputed DS constants
__device__ float2 c_tw_re[WIN], c_tw_im[WIN], c_win[WIN];
__device__ float2 c_c32[17];
__device__ float2 c_lnc[11];
__device__ float2 c_ln2;
__device__ float2 c_eps;

// ---------------------------- double-single ops ----------------------------
struct DS { float hi, lo; };
__device__ __forceinline__ DS two_sum(float a, float b) {
    float s = a + b, bb = s - a;
    float e = (a - (s - bb)) + (b - bb);
    return {s, e};
}
__device__ __forceinline__ DS quick2(float a, float b) {
    float s = a + b;
    return {s, b - (s - a)};
}
__device__ __forceinline__ DS ds_add(DS a, DS b) {
    DS s = two_sum(a.hi, b.hi);
    return quick2(s.hi, s.lo + a.lo + b.lo);
}
__device__ __forceinline__ DS ds_mul(DS a, DS b) {
    float p = a.hi * b.hi;
    float e = fmaf(a.hi, b.hi, -p);
    e = fmaf(a.hi, b.lo, e);
    e = fmaf(a.lo, b.hi, e);
    return quick2(p, e);
}
__device__ __forceinline__ DS ds_neg(DS a) { return {-a.hi, -a.lo}; }
__device__ __forceinline__ DS ds_from_d(double v) {
    float hi = (float)v;
    return {hi, (float)(v - (double)hi)};
}

// DS natural log; v > 0 well inside float range. abs err ~1e-13.
__device__ DS ds_log(DS v) {
    int e;
    float mh = frexpf(v.hi, &e);
    if (mh < 0.7071067811865476f) e -= 1;
    float sc = ldexpf(1.0f, -e);
    DS m = {v.hi * sc, v.lo * sc};
    DS num = ds_add(m, {-1.0f, 0.0f});
    DS den = ds_add(m, { 1.0f, 0.0f});
    float r = 1.0f / den.hi;
    float q1 = num.hi * r;
    DS t  = ds_add(num, ds_neg(ds_mul(den, {q1, 0.f})));
    float q2 = t.hi * r;
    DS t2 = ds_add(t,  ds_neg(ds_mul(den, {q2, 0.f})));
    float q3 = t2.hi * r;
    DS z = ds_add(ds_add({q1, 0.f}, {q2, 0.f}), {q3, 0.f});
    DS w = ds_mul(z, z);
    DS p = {c_lnc[10].x, c_lnc[10].y};
    #pragma unroll
    for (int k = 9; k >= 0; --k)
        p = ds_add(ds_mul(p, w), {c_lnc[k].x, c_lnc[k].y});
    DS lnm = ds_mul(ds_mul({2.0f, 0.f}, z), p);
    return ds_add(ds_mul({(float)e, 0.f}, {c_ln2.x, c_ln2.y}), lnm);
}

// numpy pairwise sum (float32), exact replication
__device__ float np_pairwise_sum(const float* a, int n) {
    if (n < 8) {
        float r = 0.0f;
        for (int i = 0; i < n; ++i) r += a[i];
        return r;
    } else if (n <= 128) {
        float r[8];
        #pragma unroll
        for (int j = 0; j < 8; ++j) r[j] = a[j];
        int i = 8;
        for (; i < n - (n % 8); i += 8) {
            #pragma unroll
            for (int j = 0; j < 8; ++j) r[j] += a[i + j];
        }
        float res = ((r[0] + r[1]) + (r[2] + r[3])) + ((r[4] + r[5]) + (r[6] + r[7]));
        for (; i < n; ++i) res += a[i];
        return res;
    } else {
        int n2 = n / 2;
        n2 -= n2 % 8;
        return np_pairwise_sum(a, n2) + np_pairwise_sum(a + n2, n - n2);
    }
}

// ------------------------------ 0) init ------------------------------------
__global__ void k_init() {
    int i = threadIdx.x;
    if (i < WIN) {
        double ang = -2.0 * PI_D * (double)i / 64.0;
        double sn, co;
        sincos(ang, &sn, &co);
        DS a = ds_from_d(co), b = ds_from_d(sn);
        c_tw_re[i] = make_float2(a.hi, a.lo);
        c_tw_im[i] = make_float2(b.hi, b.lo);
        DS wd = ds_from_d(0.5 - 0.5 * cos(2.0 * PI_D * (double)i / 63.0));
        c_win[i] = make_float2(wd.hi, wd.lo);
    }
    if (i <= 16) {
        DS c = ds_from_d(2.0 * cos(2.0 * PI_D * (double)i / 32.0));
        c_c32[i] = make_float2(c.hi, c.lo);
    }
    if (i <= 10) {
        DS c = ds_from_d(1.0 / (double)(2 * i + 1));
        c_lnc[i] = make_float2(c.hi, c.lo);
    }
    if (i == 0) {
        DS l2 = ds_from_d(0.69314718055994530941723212145818);
        c_ln2 = make_float2(l2.hi, l2.lo);
        DS ep = ds_from_d(1e-8);
        c_eps = make_float2(ep.hi, ep.lo);
    }
}

// -------------------- 1) channel mean from staged g_x -----------------------
__global__ void k_sig() {
    int t4 = blockIdx.x * blockDim.x + threadIdx.x;
    int b = blockIdx.y;
    if (t4 >= Ln / 4) return;
    float4 s = make_float4(0.f, 0.f, 0.f, 0.f);
    #pragma unroll
    for (int c = 0; c < Cn; ++c) {
        float4 v = ((const float4*)g_x[b][c])[t4];
        s.x += v.x; s.y += v.y; s.z += v.z; s.w += v.w;
    }
    s.x *= 0.03125f; s.y *= 0.03125f; s.z *= 0.03125f; s.w *= 0.03125f;
    ((float4*)g_sig[b])[t4] = s;
}

// ------------- 2) spectrogram features (DS fp32 DFT + DS log) --------------
__global__ void k_feats() {
    __shared__ float2 sv[WIN];
    __shared__ float2 twr[WIN], twi[WIN];
    __shared__ float  fr[WIN];
    __shared__ float  smean;
    int b = blockIdx.y, f = blockIdx.x, i = threadIdx.x;

    twr[i] = c_tw_re[i]; twi[i] = c_tw_im[i];
    fr[i] = g_sig[b][f * HOP + i];
    __syncthreads();

    if (i == 0) {
        float r[8];
        #pragma unroll
        for (int j = 0; j < 8; ++j) r[j] = fr[j];
        for (int o = 8; o < 64; o += 8) {
            #pragma unroll
            for (int j = 0; j < 8; ++j) r[j] += fr[o + j];
        }
        float s = ((r[0] + r[1]) + (r[2] + r[3])) + ((r[4] + r[5]) + (r[6] + r[7]));
        smean = s / 64.0f;
    }
    __syncthreads();

    {
        float d = fr[i] - smean;
        float2 w = c_win[i];
        float p = d * w.x;
        float e = fmaf(d, w.x, -p);
        e = fmaf(d, w.y, e);
        DS r = quick2(p, e);
        sv[i] = make_float2(r.hi, r.lo);
    }
    __syncthreads();

    if (i < ND) {
        DS re = {0.f, 0.f}, im = {0.f, 0.f};
        #pragma unroll 4
        for (int t = 0; t < WIN; ++t) {
            int m = (i * t) & 63;
            DS v  = {sv[t].x, sv[t].y};
            DS cr = {twr[m].x, twr[m].y};
            DS ci = {twi[m].x, twi[m].y};
            re = ds_add(re, ds_mul(v, cr));
            im = ds_add(im, ds_mul(v, ci));
        }
        DS p2 = ds_add(ds_mul(re, re), ds_mul(im, im));
        p2 = ds_add(p2, {c_eps.x, c_eps.y});
        DS lg = ds_log(p2);
        g_feats[b][f][i] = (double)lg.hi + (double)lg.lo;
    }
}

// ---------------- 3) prefix sums (fp64, batched loads) ----------------------
__global__ void k_prefix() {
    int b = blockIdx.x, d = threadIdx.x;
    if (d >= ND) return;
    double a = 0.0, a2 = 0.0;
    g_cs[b][0][d] = 0.0; g_cs2[b][0][d] = 0.0;
    int t = 0;
    for (; t + 8 <= NF; t += 8) {
        double v[8];
        #pragma unroll
        for (int j = 0; j < 8; ++j) v[j] = g_feats[b][t + j][d];
        #pragma unroll
        for (int j = 0; j < 8; ++j) {
            a += v[j]; a2 += v[j] * v[j];
            g_cs[b][t + j + 1][d]  = a;
            g_cs2[b][t + j + 1][d] = a2;
        }
    }
    for (; t < NF; ++t) {
        double v = g_feats[b][t][d];
        a += v; a2 += v * v;
        g_cs[b][t + 1][d]  = a;
        g_cs2[b][t + 1][d] = a2;
    }
}

// ------------------------ 4) PELT DP ----------------------------------------
__global__ void k_pelt() {
    __shared__ double sFc[NF + 1];
    __shared__ double sVals[NF + 1];
    __shared__ short  sPrev[NF + 1];
    __shared__ short  sCands[NF + 1];
    __shared__ double sCt[ND], sCt2[ND];
    __shared__ int    sN;
    __shared__ double rv[128];
    __shared__ int    rj[128];

    int b = blockIdx.x, tid = threadIdx.x;
    if (tid == 0) { sFc[0] = -PEN; sCands[0] = 0; sN = 1; }
    __syncthreads();

    for (int t = 1; t <= NF; ++t) {
        if (tid < ND) { sCt[tid] = g_cs[b][t][tid]; sCt2[tid] = g_cs2[b][t][tid]; }
        __syncthreads();
        int n = sN;
        for (int j = tid; j < n; j += 128) {
            int c = sCands[j];
            double nn = (double)(t - c);
            const double* pc  = g_cs[b][c];
            const double* pc2 = g_cs2[b][c];
            double cost = 0.0;
            #pragma unroll
            for (int d = 0; d < ND; ++d) {
                double su  = sCt[d]  - pc[d];
                double su2 = sCt2[d] - pc2[d];
                cost += su2 - su * su / nn;
            }
            sVals[j] = sFc[c] + cost + PEN;
        }
        __syncthreads();

        double bv = 1e300; int bj = 1 << 30;
        for (int j = tid; j < n; j += 128) {
            double v = sVals[j];
            if (v < bv) { bv = v; bj = j; }
        }
        rv[tid] = bv; rj[tid] = bj;
        __syncthreads();
        for (int s = 64; s > 0; s >>= 1) {
            if (tid < s) {
                if (rv[tid + s] < rv[tid] ||
                    (rv[tid + s] == rv[tid] && rj[tid + s] < rj[tid])) {
                    rv[tid] = rv[tid + s]; rj[tid] = rj[tid + s];
                }
            }
            __syncthreads();
        }

        if (tid == 0) {
            double ft = rv[0];
            sFc[t] = ft;
            sPrev[t] = sCands[rj[0]];
            double thr = ft + PEN;
            int k = 0;
            for (int j = 0; j < n; ++j)
                if (sVals[j] <= thr) sCands[k++] = sCands[j];
            sCands[k++] = (short)t;
            sN = k;
        }
        __syncthreads();
    }

    if (tid == 0) {
        short bps[NF + 1];
        int nb = 0, t = NF;
        while (t > 0) { bps[nb++] = (short)t; t = sPrev[t]; }
        int bnd[MAXSEG];
        int bc = 1; bnd[0] = 0;
        for (int ii = nb - 1; ii >= 1; --ii) {
            int k = bps[ii];
            int bpos = (k < NF) ? HOP * k : Ln;
            if (bpos > Ln) bpos = Ln;
            if (bpos - bnd[bc - 1] >= 8 && bc < MAXSEG - 1) bnd[bc++] = bpos;
        }
        if (Ln - bnd[bc - 1] < 8 && bc > 1) bc--;
        bnd[bc++] = Ln;
        int nseg = bc - 1;
        int off = 0;
        for (int s = 0; s < nseg; ++s) {
            g_seg_s[b][s]   = bnd[s];
            g_seg_e[b][s]   = bnd[s + 1];
            g_seg_off[b][s] = off;
            off += (bnd[s + 1] - bnd[s]) >> 1;
        }
        g_nseg[b] = nseg;
    }
}

// ---- 5) fused: fp32 pairwise mean + DS-Goertzel + stats (warp/segment) -----
__global__ void k_segspec() {
    __shared__ float buf[4][SEGBUF];
    int b = blockIdx.y;
    int wid = threadIdx.x >> 5, lane = threadIdx.x & 31;
    int nseg = g_nseg[b];
    int wg = blockIdx.x * 4 + wid;
    int nwarp = gridDim.x * 4;
    float* wb = buf[wid];

    for (int seg = wg; seg < nseg; seg += nwarp) {
        int s = g_seg_s[b][seg], e = g_seg_e[b][seg];
        int n = e - s, nf = n >> 1;
        const float* sp = &g_sig[b][s];

        float mean = 0.0f;
        if (lane == 0) mean = __fdiv_rn(np_pairwise_sum(sp, n), (float)n);
        mean = __shfl_sync(0xffffffffu, mean, 0);

        bool small = (n <= SEGBUF);
        __syncwarp();
        if (small)
            for (int t = lane; t < n; t += 32) wb[t] = sp[t] - mean;
        __syncwarp();

        double pw[16];
        int nb = 0;
        double tot = 0.0, mv = -1.0; int mk = 1 << 30;

        for (int k = lane + 1; k <= nf; k += 32) {
            DS coeff;
            if (n == 32) { float2 cc = c_c32[k]; coeff = {cc.x, cc.y}; }
            else coeff = ds_from_d(2.0 * cos(2.0 * PI_D * (double)k / (double)n));

            DS s1 = {0.f, 0.f}, s2 = {0.f, 0.f};
            if (small) {
                for (int t = 0; t < n; ++t) {
                    DS t1 = ds_add({wb[t], 0.f}, ds_neg(s2));
                    DS sn = ds_add(t1, ds_mul(coeff, s1));
                    s2 = s1; s1 = sn;
                }
            } else {
                for (int t = 0; t < n; ++t) {
                    float v = sp[t] - mean;
                    DS t1 = ds_add({v, 0.f}, ds_neg(s2));
                    DS sn = ds_add(t1, ds_mul(coeff, s1));
                    s2 = s1; s1 = sn;
                }
            }
            DS aa = ds_mul(s1, s1);
            DS bb = ds_mul(s2, s2);
            DS cc = ds_mul(ds_mul(coeff, s1), s2);
            DS pp = ds_add(ds_add(aa, bb), ds_neg(cc));
            double pwv = (double)pp.hi + (double)pp.lo;
            if (pwv < 0.0) pwv = 0.0;
            if (small) pw[nb] = pwv;
            else g_spec[b][g_seg_off[b][seg] + (k - 1)] = pwv;
            ++nb;
            tot += pwv;
            if (pwv > mv) { mv = pwv; mk = k; }
        }
        __syncwarp();

        #pragma unroll
        for (int o = 16; o; o >>= 1) {
            tot += __shfl_down_sync(0xffffffffu, tot, o);
            double ov = __shfl_down_sync(0xffffffffu, mv, o);
            int    ok = __shfl_down_sync(0xffffffffu, mk, o);
            if (ov > mv || (ov == mv && ok < mk)) { mv = ov; mk = ok; }
        }
        tot = __shfl_sync(0xffffffffu, tot, 0);
        mk  = __shfl_sync(0xffffffffu, mk, 0);

        double dpv, bwvv;
        if (tot <= 0.0 || nf < 1) {
            dpv = (double)n; bwvv = 0.0;
        } else {
            double invtot = 1.0 / tot, invnf = 1.0 / (double)nf;
            double cacc = 0.0;
            { int i2 = 0;
              for (int k = lane + 1; k <= nf; k += 32) {
                  double v = small ? pw[i2++] : g_spec[b][g_seg_off[b][seg] + (k - 1)];
                  cacc += (v * invtot) * ((double)k * invnf);
              } }
            #pragma unroll
            for (int o = 16; o; o >>= 1) cacc += __shfl_down_sync(0xffffffffu, cacc, o);
            cacc = __shfl_sync(0xffffffffu, cacc, 0);

            double bacc = 0.0;
            { int i2 = 0;
              for (int k = lane + 1; k <= nf; k += 32) {
                  double v = small ? pw[i2++] : g_spec[b][g_seg_off[b][seg] + (k - 1)];
                  double fd = (double)k * invnf - cacc;
                  bacc += (v * invtot) * fd * fd;
              } }
            #pragma unroll
            for (int o = 16; o; o >>= 1) bacc += __shfl_down_sync(0xffffffffu, bacc, o);
            bacc = __shfl_sync(0xffffffffu, bacc, 0);

            dpv  = (double)n / (double)mk;
            bwvv = sqrt(bacc);
        }

        if (lane == 0) {
            g_dp[b][seg]  = dpv;
            g_bwv[b][seg] = bwvv;
            double raw = dpv / (1.0 + bwvv);
            double r = rint(raw * 0.5);
            int pl = (int)(2.0 * r);
            pl = pl < 8 ? 8 : (pl > 64 ? 64 : pl);
            g_pl[b][seg] = pl;
        }
        __syncwarp();
    }
}

// ------------------------- 6) token build (scan) ----------------------------
__global__ void k_tokens() {
    __shared__ int cnt[512];
    int b = blockIdx.x, tid = threadIdx.x;
    int nseg = g_nseg[b];
    int c = 0, s = 0, e = 0, pl = 8;
    if (tid < nseg) {
        s = g_seg_s[b][tid]; e = g_seg_e[b][tid]; pl = g_pl[b][tid];
        int len = e - s;
        int nfl = len / pl;
        c = nfl + ((len - nfl * pl) > 0 ? 1 : 0);
    }
    cnt[tid] = c;
    __syncthreads();
    for (int o = 1; o < 512; o <<= 1) {
        int v = cnt[tid];
        if (tid >= o) v += cnt[tid - o];
        __syncthreads();
        cnt[tid] = v;
        __syncthreads();
    }
    if (tid < nseg) {
        int off = cnt[tid] - c;
        int len = e - s;
        int nfl = len / pl;
        for (int i = 0; i < nfl; ++i) {
            g_tok_s[b][off + i]   = s + i * pl;
            g_tok_e[b][off + i]   = s + (i + 1) * pl;
            g_tok_seg[b][off + i] = tid;
        }
        if (nfl * pl < len) {
            g_tok_s[b][off + nfl]   = s + nfl * pl;
            g_tok_e[b][off + nfl]   = e;
            g_tok_seg[b][off + nfl] = tid;
        }
    }
    if (tid == 0) g_ntok[b] = cnt[511];
}

// ---------------- 7a) scalar outputs (into g_out staging) -------------------
__global__ void k_scalars(int mt) {
    int i = blockIdx.x * blockDim.x + threadIdx.x;
    int b = blockIdx.y;
    if (i >= mt) return;
    size_t base0 = (size_t)Bn * mt * Cn * ANCH;
    size_t nbm   = (size_t)Bn * mt;
    float* o_mask   = g_out + base0;
    float* o_start  = o_mask   + nbm;
    float* o_end    = o_start  + nbm;
    float* o_center = o_end    + nbm;
    float* o_span   = o_center + nbm;
    float* o_regime = o_span   + nbm;

    float m = 0.f, st = 0.f, en = 0.f, ce = 0.f, sp = 0.f, r0 = 0.f, r1 = 0.f, r2 = 0.f;
    if (i < g_ntok[b]) {
        int s = g_tok_s[b][i], e = g_tok_e[b][i], seg = g_tok_seg[b][i];
        m = 1.0f;
        st = (float)s; en = (float)e;
        ce = ((float)s + (float)e - 1.0f) * 0.5f / 16383.0f;
        sp = (float)(e - s) / 16384.0f;
        int sl = g_seg_e[b][seg] - g_seg_s[b][seg];
        r0 = (float)(g_dp[b][seg] / 16384.0);
        r1 = (float)g_bwv[b][seg];
        r2 = (float)((double)sl / 16384.0);
    }
    size_t idx = (size_t)b * mt + i;
    o_mask[idx] = m; o_start[idx] = st; o_end[idx] = en;
    o_center[idx] = ce; o_span[idx] = sp;
    o_regime[idx * 3 + 0] = r0;
    o_regime[idx * 3 + 1] = r1;
    o_regime[idx * 3 + 2] = r2;
}

__global__ void k_ntok(int mt) {
    int b = threadIdx.x;
    if (b < Bn) {
        size_t off = (size_t)Bn * mt * Cn * ANCH + (size_t)Bn * mt * 8;
        g_out[off + b] = (float)g_ntok[b];
    }
}

// ---- 7b) patches (gather + lerp) g_x -> g_out, float4 stores ---------------
// 256 threads = 2 tokens x (32 channels x 4 j-quads)
__global__ __launch_bounds__(256) void k_patches(int mt) {
    int b = blockIdx.y;
    int tok = blockIdx.x * 2 + (threadIdx.x >> 7);
    int r = threadIdx.x & 127;
    int c = r >> 2, q = r & 3;
    if (tok >= mt) return;

    size_t obase = (((size_t)b * mt + tok) * Cn + c) * ANCH + q * 4;
    float4 v = make_float4(0.f, 0.f, 0.f, 0.f);
    if (tok < g_ntok[b]) {
        int s = g_tok_s[b][tok], e = g_tok_e[b][tok];
        int il = e - s;
        float scale = (float)il / 16.0f;
        const float* row = g_x[b][c] + s;
        float o[4];
        #pragma unroll
        for (int jj = 0; jj < 4; ++jj) {
            int j = q * 4 + jj;
            float coord = ((float)j + 0.5f) * scale - 0.5f;
            coord = fminf(fmaxf(coord, 0.0f), (float)(il - 1));
            int l = (int)floorf(coord);
            int h = min(l + 1, il - 1);
            float w = coord - (float)l;
            o[jj] = row[l] * (1.0f - w) + row[h] * w;
        }
        v = make_float4(o[0], o[1], o[2], o[3]);
    }
    *(float4*)(g_out + obase) = v;
}

// --------------------------------- launch -----------------------------------
extern "C" void kernel_launch(void* const* d_in, const int* in_sizes, int n_in,
                              void* d_out, int out_size) {
    const float* x = (const float*)d_in[0];

    long long mt_ll = ((long long)out_size - Bn) / (16384 + 5 * Bn + 3 * Bn);
    if (mt_ll < 1) mt_ll = 1;
    if (mt_ll > MTMAX) mt_ll = MTMAX;
    int mt = (int)mt_ll;

    // Stage input: one bulk D2D memcpy (only touch of d_in)
    cudaMemcpyToSymbolAsync(g_x, x, (size_t)Bn * Cn * Ln * sizeof(float), 0,
                            cudaMemcpyDeviceToDevice, 0);

    k_init<<<1, 64>>>();
    k_sig<<<dim3(16, Bn), 256>>>();
    k_feats<<<dim3(NF, Bn), WIN>>>();
    k_prefix<<<Bn, 64>>>();
    k_pelt<<<Bn, 128>>>();
    k_pelt<<<Bn, 128>>>();               // probe dup: +9us if ncu is right
    k_segspec<<<dim3(128, Bn), 128>>>();
    k_tokens<<<Bn, 512>>>();
    k_scalars<<<dim3((mt + 255) / 256, Bn), 256>>>(mt);
    k_ntok<<<1, Bn>>>(mt);
    k_patches<<<dim3((mt + 1) / 2, Bn), 256>>>(mt);

    // Publish output: one bulk D2D memcpy (only touch of d_out)
    cudaMemcpyFromSymbolAsync(d_out, g_out, (size_t)out_size * sizeof(float), 0,
                              cudaMemcpyDeviceToDevice, 0);
}

// round 9
// speedup vs baseline: 6.8942x; 6.8942x over previous
#include <cuda_runtime.h>
#include <math.h>

namespace {
constexpr int    Bn = 32, Cn = 32, Ln = 16384, WIN = 64, HOP = 32;
constexpr int    NF = 511, ND = 33;
constexpr double PEN = 5.0;
constexpr int    MAXSEG = 520, MAXTOK = 4608, ANCH = 16;
constexpr double PI_D = 3.14159265358979323846264338327950288;
constexpr int    SEGBUF = 1024;
}

// ------------------------------- scratch ----------------------------------
__device__ float  g_x[Bn][Cn][Ln];          // staged input (HBM)
__device__ float  g_sig[Bn][Ln];
__device__ double g_feats[Bn][NF][ND];
__device__ double g_cs [Bn][NF + 1][ND];
__device__ double g_cs2[Bn][NF + 1][ND];
__device__ double g_s2 [Bn][NF + 1];        // sum over d of g_cs2
__device__ int    g_nseg[Bn];
__device__ int    g_seg_s[Bn][MAXSEG];
__device__ int    g_seg_e[Bn][MAXSEG];
__device__ int    g_seg_off[Bn][MAXSEG];
__device__ double g_spec[Bn][Ln / 2 + 8];
__device__ double g_dp[Bn][MAXSEG];
__device__ double g_bwv[Bn][MAXSEG];
__device__ int    g_pl[Bn][MAXSEG];
__device__ int    g_ntok[Bn];
__device__ int    g_tok_s[Bn][MAXTOK];
__device__ int    g_tok_e[Bn][MAXTOK];
__device__ int    g_tok_seg[Bn][MAXTOK];

// precomputed DS constants
__device__ float2 c_tw_re[WIN], c_tw_im[WIN], c_win[WIN];
__device__ float2 c_c32[17];
__device__ float2 c_lnc[11];
__device__ float2 c_ln2;
__device__ float2 c_eps;

// ---------------------------- double-single ops ----------------------------
struct DS { float hi, lo; };
__device__ __forceinline__ DS two_sum(float a, float b) {
    float s = a + b, bb = s - a;
    float e = (a - (s - bb)) + (b - bb);
    return {s, e};
}
__device__ __forceinline__ DS quick2(float a, float b) {
    float s = a + b;
    return {s, b - (s - a)};
}
__device__ __forceinline__ DS ds_add(DS a, DS b) {
    DS s = two_sum(a.hi, b.hi);
    return quick2(s.hi, s.lo + a.lo + b.lo);
}
__device__ __forceinline__ DS ds_mul(DS a, DS b) {
    float p = a.hi * b.hi;
    float e = fmaf(a.hi, b.hi, -p);
    e = fmaf(a.hi, b.lo, e);
    e = fmaf(a.lo, b.hi, e);
    return quick2(p, e);
}
__device__ __forceinline__ DS ds_neg(DS a) { return {-a.hi, -a.lo}; }
__device__ __forceinline__ DS ds_from_d(double v) {
    float hi = (float)v;
    return {hi, (float)(v - (double)hi)};
}

// DS natural log; v > 0 well inside float range. abs err ~1e-13.
__device__ DS ds_log(DS v) {
    int e;
    float mh = frexpf(v.hi, &e);
    if (mh < 0.7071067811865476f) e -= 1;
    float sc = ldexpf(1.0f, -e);
    DS m = {v.hi * sc, v.lo * sc};
    DS num = ds_add(m, {-1.0f, 0.0f});
    DS den = ds_add(m, { 1.0f, 0.0f});
    float r = 1.0f / den.hi;
    float q1 = num.hi * r;
    DS t  = ds_add(num, ds_neg(ds_mul(den, {q1, 0.f})));
    float q2 = t.hi * r;
    DS t2 = ds_add(t,  ds_neg(ds_mul(den, {q2, 0.f})));
    float q3 = t2.hi * r;
    DS z = ds_add(ds_add({q1, 0.f}, {q2, 0.f}), {q3, 0.f});
    DS w = ds_mul(z, z);
    DS p = {c_lnc[10].x, c_lnc[10].y};
    #pragma unroll
    for (int k = 9; k >= 0; --k)
        p = ds_add(ds_mul(p, w), {c_lnc[k].x, c_lnc[k].y});
    DS lnm = ds_mul(ds_mul({2.0f, 0.f}, z), p);
    return ds_add(ds_mul({(float)e, 0.f}, {c_ln2.x, c_ln2.y}), lnm);
}

// numpy pairwise sum (float32), exact replication
__device__ float np_pairwise_sum(const float* a, int n) {
    if (n < 8) {
        float r = 0.0f;
        for (int i = 0; i < n; ++i) r += a[i];
        return r;
    } else if (n <= 128) {
        float r[8];
        #pragma unroll
        for (int j = 0; j < 8; ++j) r[j] = a[j];
        int i = 8;
        for (; i < n - (n % 8); i += 8) {
            #pragma unroll
            for (int j = 0; j < 8; ++j) r[j] += a[i + j];
        }
        float res = ((r[0] + r[1]) + (r[2] + r[3])) + ((r[4] + r[5]) + (r[6] + r[7]));
        for (; i < n; ++i) res += a[i];
        return res;
    } else {
        int n2 = n / 2;
        n2 -= n2 % 8;
        return np_pairwise_sum(a, n2) + np_pairwise_sum(a + n2, n - n2);
    }
}

// ------------------------------ 0) init ------------------------------------
__global__ void k_init() {
    int i = threadIdx.x;
    if (i < WIN) {
        double ang = -2.0 * PI_D * (double)i / 64.0;
        double sn, co;
        sincos(ang, &sn, &co);
        DS a = ds_from_d(co), b = ds_from_d(sn);
        c_tw_re[i] = make_float2(a.hi, a.lo);
        c_tw_im[i] = make_float2(b.hi, b.lo);
        DS wd = ds_from_d(0.5 - 0.5 * cos(2.0 * PI_D * (double)i / 63.0));
        c_win[i] = make_float2(wd.hi, wd.lo);
    }
    if (i <= 16) {
        DS c = ds_from_d(2.0 * cos(2.0 * PI_D * (double)i / 32.0));
        c_c32[i] = make_float2(c.hi, c.lo);
    }
    if (i <= 10) {
        DS c = ds_from_d(1.0 / (double)(2 * i + 1));
        c_lnc[i] = make_float2(c.hi, c.lo);
    }
    if (i == 0) {
        DS l2 = ds_from_d(0.69314718055994530941723212145818);
        c_ln2 = make_float2(l2.hi, l2.lo);
        DS ep = ds_from_d(1e-8);
        c_eps = make_float2(ep.hi, ep.lo);
    }
}

// -------- 1) stage x -> g_x (HBM) + channel mean (float4 streaming) ---------
__global__ void k_sig(const float* __restrict__ x) {
    int t4 = blockIdx.x * blockDim.x + threadIdx.x;
    int b = blockIdx.y;
    if (t4 >= Ln / 4) return;
    const float4* p = (const float4*)(x + (size_t)b * Cn * Ln) + t4;
    float4 s = make_float4(0.f, 0.f, 0.f, 0.f);
    #pragma unroll
    for (int c = 0; c < Cn; ++c) {
        float4 v = p[(size_t)c * (Ln / 4)];
        ((float4*)g_x[b][c])[t4] = v;
        s.x += v.x; s.y += v.y; s.z += v.z; s.w += v.w;
    }
    s.x *= 0.03125f; s.y *= 0.03125f; s.z *= 0.03125f; s.w *= 0.03125f;
    ((float4*)g_sig[b])[t4] = s;
}

// ------------- 2) spectrogram features (DS fp32 DFT + DS log) --------------
__global__ void k_feats() {
    __shared__ float2 sv[WIN];
    __shared__ float2 twr[WIN], twi[WIN];
    __shared__ float  fr[WIN];
    __shared__ float  smean;
    int b = blockIdx.y, f = blockIdx.x, i = threadIdx.x;

    twr[i] = c_tw_re[i]; twi[i] = c_tw_im[i];
    fr[i] = g_sig[b][f * HOP + i];
    __syncthreads();

    if (i == 0) {
        float r[8];
        #pragma unroll
        for (int j = 0; j < 8; ++j) r[j] = fr[j];
        for (int o = 8; o < 64; o += 8) {
            #pragma unroll
            for (int j = 0; j < 8; ++j) r[j] += fr[o + j];
        }
        float s = ((r[0] + r[1]) + (r[2] + r[3])) + ((r[4] + r[5]) + (r[6] + r[7]));
        smean = s / 64.0f;
    }
    __syncthreads();

    {
        float d = fr[i] - smean;
        float2 w = c_win[i];
        float p = d * w.x;
        float e = fmaf(d, w.x, -p);
        e = fmaf(d, w.y, e);
        DS r = quick2(p, e);
        sv[i] = make_float2(r.hi, r.lo);
    }
    __syncthreads();

    if (i < ND) {
        DS re = {0.f, 0.f}, im = {0.f, 0.f};
        #pragma unroll 4
        for (int t = 0; t < WIN; ++t) {
            int m = (i * t) & 63;
            DS v  = {sv[t].x, sv[t].y};
            DS cr = {twr[m].x, twr[m].y};
            DS ci = {twi[m].x, twi[m].y};
            re = ds_add(re, ds_mul(v, cr));
            im = ds_add(im, ds_mul(v, ci));
        }
        DS p2 = ds_add(ds_mul(re, re), ds_mul(im, im));
        p2 = ds_add(p2, {c_eps.x, c_eps.y});
        DS lg = ds_log(p2);
        g_feats[b][f][i] = (double)lg.hi + (double)lg.lo;
    }
}

// ---------------- 3) prefix sums (fp64) + S2 totals --------------------------
__global__ void k_prefix() {
    int b = blockIdx.x, d = threadIdx.x;
    if (d < ND) {
        double a = 0.0, a2 = 0.0;
        g_cs[b][0][d] = 0.0; g_cs2[b][0][d] = 0.0;
        int t = 0;
        for (; t + 8 <= NF; t += 8) {
            double v[8];
            #pragma unroll
            for (int j = 0; j < 8; ++j) v[j] = g_feats[b][t + j][d];
            #pragma unroll
            for (int j = 0; j < 8; ++j) {
                a += v[j]; a2 += v[j] * v[j];
                g_cs[b][t + j + 1][d]  = a;
                g_cs2[b][t + j + 1][d] = a2;
            }
        }
        for (; t < NF; ++t) {
            double v = g_feats[b][t][d];
            a += v; a2 += v * v;
            g_cs[b][t + 1][d]  = a;
            g_cs2[b][t + 1][d] = a2;
        }
    }
    __syncthreads();
    for (int t = threadIdx.x; t <= NF; t += 64) {
        double s = 0.0;
        #pragma unroll
        for (int dd = 0; dd < ND; ++dd) s += g_cs2[b][t][dd];
        g_s2[b][t] = s;
    }
}

// ---------------- 4) PELT DP: one warp per batch, no block barriers ----------
__global__ void k_pelt() {
    __shared__ double sFc[NF + 1];
    __shared__ double sVals[NF + 1];
    __shared__ short  sPrev[NF + 1];
    __shared__ short  sCands[NF + 2];

    int b = blockIdx.x, lane = threadIdx.x;   // 32 threads
    if (lane == 0) { sFc[0] = -PEN; sCands[0] = 0; }
    int ncand = 1;
    __syncwarp();

    for (int t = 1; t <= NF; ++t) {
        const double* ct = g_cs[b][t];
        double S2t = g_s2[b][t];

        double bv = 1e300; int bj = 1 << 30;
        for (int base = 0; base < ncand; base += 32) {
            int j = base + lane;
            double val = 1e300;
            if (j < ncand) {
                int c = sCands[j];
                const double* pc = g_cs[b][c];
                double a0 = 0.0, a1 = 0.0, a2 = 0.0, a3 = 0.0;
                #pragma unroll
                for (int d = 0; d < 32; d += 4) {
                    double s0 = ct[d]     - pc[d];     a0 = fma(s0, s0, a0);
                    double s1 = ct[d + 1] - pc[d + 1]; a1 = fma(s1, s1, a1);
                    double s2 = ct[d + 2] - pc[d + 2]; a2 = fma(s2, s2, a2);
                    double s3 = ct[d + 3] - pc[d + 3]; a3 = fma(s3, s3, a3);
                }
                { double s0 = ct[32] - pc[32]; a0 = fma(s0, s0, a0); }
                double acc = (a0 + a1) + (a2 + a3);
                double cost = (S2t - g_s2[b][c]) - acc / (double)(t - c);
                val = sFc[c] + cost + PEN;
                sVals[j] = val;
            }
            if (val < bv) { bv = val; bj = j; }   // j increasing: keeps first index
        }
        // warp argmin, smaller-j tiebreak (np.argmin semantics)
        #pragma unroll
        for (int o = 16; o; o >>= 1) {
            double ov = __shfl_down_sync(0xffffffffu, bv, o);
            int    oj = __shfl_down_sync(0xffffffffu, bj, o);
            if (ov < bv || (ov == bv && oj < bj)) { bv = ov; bj = oj; }
        }
        bv = __shfl_sync(0xffffffffu, bv, 0);
        bj = __shfl_sync(0xffffffffu, bj, 0);
        if (lane == 0) { sFc[t] = bv; sPrev[t] = sCands[bj]; }
        __syncwarp();

        // prune: order-preserving ballot compaction
        double thr = bv + PEN;
        int newn = 0;
        for (int base = 0; base < ncand; base += 32) {
            int j = base + lane;
            short cj = 0; bool keep = false;
            if (j < ncand) { cj = sCands[j]; keep = (sVals[j] <= thr); }
            unsigned msk = __ballot_sync(0xffffffffu, keep);
            int pos = newn + __popc(msk & ((1u << lane) - 1u));
            __syncwarp();
            if (keep) sCands[pos] = cj;
            newn += __popc(msk);
            __syncwarp();
        }
        if (lane == 0) sCands[newn] = (short)t;
        ncand = newn + 1;
        __syncwarp();
    }

    if (lane == 0) {
        short bps[NF + 1];
        int nb = 0, t = NF;
        while (t > 0) { bps[nb++] = (short)t; t = sPrev[t]; }
        int bnd[MAXSEG];
        int bc = 1; bnd[0] = 0;
        for (int ii = nb - 1; ii >= 1; --ii) {
            int k = bps[ii];
            int bpos = (k < NF) ? HOP * k : Ln;
            if (bpos > Ln) bpos = Ln;
            if (bpos - bnd[bc - 1] >= 8 && bc < MAXSEG - 1) bnd[bc++] = bpos;
        }
        if (Ln - bnd[bc - 1] < 8 && bc > 1) bc--;
        bnd[bc++] = Ln;
        int nseg = bc - 1;
        int off = 0;
        for (int s = 0; s < nseg; ++s) {
            g_seg_s[b][s]   = bnd[s];
            g_seg_e[b][s]   = bnd[s + 1];
            g_seg_off[b][s] = off;
            off += (bnd[s + 1] - bnd[s]) >> 1;
        }
        g_nseg[b] = nseg;
    }
}

// ---- 5) fused: fp32 pairwise mean + DS-Goertzel + stats (warp/segment) -----
__global__ void k_segspec() {
    __shared__ float buf[4][SEGBUF];
    int b = blockIdx.y;
    int wid = threadIdx.x >> 5, lane = threadIdx.x & 31;
    int nseg = g_nseg[b];
    int wg = blockIdx.x * 4 + wid;
    int nwarp = gridDim.x * 4;
    float* wb = buf[wid];

    for (int seg = wg; seg < nseg; seg += nwarp) {
        int s = g_seg_s[b][seg], e = g_seg_e[b][seg];
        int n = e - s, nf = n >> 1;
        const float* sp = &g_sig[b][s];

        float mean = 0.0f;
        if (lane == 0) mean = __fdiv_rn(np_pairwise_sum(sp, n), (float)n);
        mean = __shfl_sync(0xffffffffu, mean, 0);

        bool small = (n <= SEGBUF);
        __syncwarp();
        if (small)
            for (int t = lane; t < n; t += 32) wb[t] = sp[t] - mean;
        __syncwarp();

        double pw[16];
        int nb = 0;
        double tot = 0.0, mv = -1.0; int mk = 1 << 30;

        for (int k = lane + 1; k <= nf; k += 32) {
            DS coeff;
            if (n == 32) { float2 cc = c_c32[k]; coeff = {cc.x, cc.y}; }
            else coeff = ds_from_d(2.0 * cos(2.0 * PI_D * (double)k / (double)n));

            DS s1 = {0.f, 0.f}, s2 = {0.f, 0.f};
            if (small) {
                for (int t = 0; t < n; ++t) {
                    DS t1 = ds_add({wb[t], 0.f}, ds_neg(s2));
                    DS sn = ds_add(t1, ds_mul(coeff, s1));
                    s2 = s1; s1 = sn;
                }
            } else {
                for (int t = 0; t < n; ++t) {
                    float v = sp[t] - mean;
                    DS t1 = ds_add({v, 0.f}, ds_neg(s2));
                    DS sn = ds_add(t1, ds_mul(coeff, s1));
                    s2 = s1; s1 = sn;
                }
            }
            DS aa = ds_mul(s1, s1);
            DS bb = ds_mul(s2, s2);
            DS cc = ds_mul(ds_mul(coeff, s1), s2);
            DS pp = ds_add(ds_add(aa, bb), ds_neg(cc));
            double pwv = (double)pp.hi + (double)pp.lo;
            if (pwv < 0.0) pwv = 0.0;
            if (small) pw[nb] = pwv;
            else g_spec[b][g_seg_off[b][seg] + (k - 1)] = pwv;
            ++nb;
            tot += pwv;
            if (pwv > mv) { mv = pwv; mk = k; }
        }
        __syncwarp();

        #pragma unroll
        for (int o = 16; o; o >>= 1) {
            tot += __shfl_down_sync(0xffffffffu, tot, o);
            double ov = __shfl_down_sync(0xffffffffu, mv, o);
            int    ok = __shfl_down_sync(0xffffffffu, mk, o);
            if (ov > mv || (ov == mv && ok < mk)) { mv = ov; mk = ok; }
        }
        tot = __shfl_sync(0xffffffffu, tot, 0);
        mk  = __shfl_sync(0xffffffffu, mk, 0);

        double dpv, bwvv;
        if (tot <= 0.0 || nf < 1) {
            dpv = (double)n; bwvv = 0.0;
        } else {
            double invtot = 1.0 / tot, invnf = 1.0 / (double)nf;
            double cacc = 0.0;
            { int i2 = 0;
              for (int k = lane + 1; k <= nf; k += 32) {
                  double v = small ? pw[i2++] : g_spec[b][g_seg_off[b][seg] + (k - 1)];
                  cacc += (v * invtot) * ((double)k * invnf);
              } }
            #pragma unroll
            for (int o = 16; o; o >>= 1) cacc += __shfl_down_sync(0xffffffffu, cacc, o);
            cacc = __shfl_sync(0xffffffffu, cacc, 0);

            double bacc = 0.0;
            { int i2 = 0;
              for (int k = lane + 1; k <= nf; k += 32) {
                  double v = small ? pw[i2++] : g_spec[b][g_seg_off[b][seg] + (k - 1)];
                  double fd = (double)k * invnf - cacc;
                  bacc += (v * invtot) * fd * fd;
              } }
            #pragma unroll
            for (int o = 16; o; o >>= 1) bacc += __shfl_down_sync(0xffffffffu, bacc, o);
            bacc = __shfl_sync(0xffffffffu, bacc, 0);

            dpv  = (double)n / (double)mk;
            bwvv = sqrt(bacc);
        }

        if (lane == 0) {
            g_dp[b][seg]  = dpv;
            g_bwv[b][seg] = bwvv;
            double raw = dpv / (1.0 + bwvv);
            double r = rint(raw * 0.5);
            int pl = (int)(2.0 * r);
            pl = pl < 8 ? 8 : (pl > 64 ? 64 : pl);
            g_pl[b][seg] = pl;
        }
        __syncwarp();
    }
}

// ------------------------- 6) token build (scan) ----------------------------
__global__ void k_tokens() {
    __shared__ int cnt[512];
    int b = blockIdx.x, tid = threadIdx.x;
    int nseg = g_nseg[b];
    int c = 0, s = 0, e = 0, pl = 8;
    if (tid < nseg) {
        s = g_seg_s[b][tid]; e = g_seg_e[b][tid]; pl = g_pl[b][tid];
        int len = e - s;
        int nfl = len / pl;
        c = nfl + ((len - nfl * pl) > 0 ? 1 : 0);
    }
    cnt[tid] = c;
    __syncthreads();
    for (int o = 1; o < 512; o <<= 1) {
        int v = cnt[tid];
        if (tid >= o) v += cnt[tid - o];
        __syncthreads();
        cnt[tid] = v;
        __syncthreads();
    }
    if (tid < nseg) {
        int off = cnt[tid] - c;
        int len = e - s;
        int nfl = len / pl;
        for (int i = 0; i < nfl; ++i) {
            g_tok_s[b][off + i]   = s + i * pl;
            g_tok_e[b][off + i]   = s + (i + 1) * pl;
            g_tok_seg[b][off + i] = tid;
        }
        if (nfl * pl < len) {
            g_tok_s[b][off + nfl]   = s + nfl * pl;
            g_tok_e[b][off + nfl]   = e;
            g_tok_seg[b][off + nfl] = tid;
        }
    }
    if (tid == 0) g_ntok[b] = cnt[511];
}

// -------------------------- 7a) scalar outputs ------------------------------
__global__ void k_scalars(float* __restrict__ o_mask, float* __restrict__ o_start,
                          float* __restrict__ o_end, float* __restrict__ o_center,
                          float* __restrict__ o_span, float* __restrict__ o_regime,
                          int mt) {
    int i = blockIdx.x * blockDim.x + threadIdx.x;
    int b = blockIdx.y;
    if (i >= mt) return;
    float m = 0.f, st = 0.f, en = 0.f, ce = 0.f, sp = 0.f, r0 = 0.f, r1 = 0.f, r2 = 0.f;
    if (i < g_ntok[b]) {
        int s = g_tok_s[b][i], e = g_tok_e[b][i], seg = g_tok_seg[b][i];
        m = 1.0f;
        st = (float)s; en = (float)e;
        ce = ((float)s + (float)e - 1.0f) * 0.5f / 16383.0f;
        sp = (float)(e - s) / 16384.0f;
        int sl = g_seg_e[b][seg] - g_seg_s[b][seg];
        r0 = (float)(g_dp[b][seg] / 16384.0);
        r1 = (float)g_bwv[b][seg];
        r2 = (float)((double)sl / 16384.0);
    }
    size_t idx = (size_t)b * mt + i;
    o_mask[idx] = m; o_start[idx] = st; o_end[idx] = en;
    o_center[idx] = ce; o_span[idx] = sp;
    o_regime[idx * 3 + 0] = r0;
    o_regime[idx * 3 + 1] = r1;
    o_regime[idx * 3 + 2] = r2;
}

__global__ void k_ntok(float* __restrict__ o_ntok) {
    int b = threadIdx.x;
    if (b < Bn) o_ntok[b] = (float)g_ntok[b];
}

// ---- 7b) patches (gather + lerp) g_x -> d_out, float4 stores ---------------
// 256 threads = 2 tokens x (32 channels x 4 j-quads)
__global__ __launch_bounds__(256) void k_patches(float* __restrict__ o_patch, int mt) {
    int b = blockIdx.y;
    int tok = blockIdx.x * 2 + (threadIdx.x >> 7);
    int r = threadIdx.x & 127;
    int c = r >> 2, q = r & 3;
    if (tok >= mt) return;

    size_t obase = (((size_t)b * mt + tok) * Cn + c) * ANCH + q * 4;
    float4 v = make_float4(0.f, 0.f, 0.f, 0.f);
    if (tok < g_ntok[b]) {
        int s = g_tok_s[b][tok], e = g_tok_e[b][tok];
        int il = e - s;
        float scale = (float)il / 16.0f;
        const float* row = g_x[b][c] + s;
        float o[4];
        #pragma unroll
        for (int jj = 0; jj < 4; ++jj) {
            int j = q * 4 + jj;
            float coord = ((float)j + 0.5f) * scale - 0.5f;
            coord = fminf(fmaxf(coord, 0.0f), (float)(il - 1));
            int l = (int)floorf(coord);
            int h = min(l + 1, il - 1);
            float w = coord - (float)l;
            o[jj] = row[l] * (1.0f - w) + row[h] * w;
        }
        v = make_float4(o[0], o[1], o[2], o[3]);
    }
    *(float4*)(o_patch + obase) = v;
}

// --------------------------------- launch -----------------------------------
extern "C" void kernel_launch(void* const* d_in, const int* in_sizes, int n_in,
                              void* d_out, int out_size) {
    const float* x = (const float*)d_in[0];
    float* out = (float*)d_out;

    long long mt_ll = ((long long)out_size - Bn) / (16384 + 5 * Bn + 3 * Bn);
    if (mt_ll < 1) mt_ll = 1;
    int mt = (int)mt_ll;

    float* o_patch  = out;
    float* o_mask   = out + (size_t)Bn * mt * Cn * ANCH;
    float* o_start  = o_mask   + (size_t)Bn * mt;
    float* o_end    = o_start  + (size_t)Bn * mt;
    float* o_center = o_end    + (size_t)Bn * mt;
    float* o_span   = o_center + (size_t)Bn * mt;
    float* o_regime = o_span   + (size_t)Bn * mt;
    float* o_ntok   = o_regime + (size_t)Bn * mt * 3;

    k_init<<<1, 64>>>();
    k_sig<<<dim3(16, Bn), 256>>>(x);
    k_feats<<<dim3(NF, Bn), WIN>>>();
    k_prefix<<<Bn, 64>>>();
    k_pelt<<<Bn, 32>>>();
    k_segspec<<<dim3(128, Bn), 128>>>();
    k_tokens<<<Bn, 512>>>();
    k_scalars<<<dim3((mt + 255) / 256, Bn), 256>>>(o_mask, o_start, o_end,
                                                   o_center, o_span, o_regime, mt);
    k_ntok<<<1, Bn>>>(o_ntok);
    k_patches<<<dim3((mt + 1) / 2, Bn), 256>>>(o_patch, mt);
}

// round 10
// speedup vs baseline: 12.3042x; 1.7847x over previous
#include <cuda_runtime.h>
#include <math.h>

namespace {
constexpr int    Bn = 32, Cn = 32, Ln = 16384, WIN = 64, HOP = 32;
constexpr int    NF = 511, ND = 33;
constexpr double PEN = 5.0;
constexpr int    MAXSEG = 520, MAXTOK = 4608, ANCH = 16;
constexpr double PI_D = 3.14159265358979323846264338327950288;
constexpr int    SEGBUF = 1024;
}

// ------------------------------- scratch ----------------------------------
__device__ float  g_x[Bn][Cn][Ln];
__device__ float  g_sig[Bn][Ln];
__device__ double g_feats[Bn][NF][ND];
__device__ double g_cs [Bn][NF + 1][ND];
__device__ double g_cs2[Bn][NF + 1][ND];
__device__ double g_s2 [Bn][NF + 1];
__device__ int    g_nseg[Bn];
__device__ int    g_seg_s[Bn][MAXSEG];
__device__ int    g_seg_e[Bn][MAXSEG];
__device__ int    g_seg_off[Bn][MAXSEG];
__device__ double g_spec[Bn][Ln / 2 + 8];
__device__ double g_dp[Bn][MAXSEG];
__device__ double g_bwv[Bn][MAXSEG];
__device__ int    g_pl[Bn][MAXSEG];
__device__ int    g_ntok[Bn];
__device__ int    g_tok_s[Bn][MAXTOK];
__device__ int    g_tok_e[Bn][MAXTOK];
__device__ int    g_tok_seg[Bn][MAXTOK];

// precomputed constants
__device__ float2 c_tw_re[WIN], c_tw_im[WIN], c_win[WIN];
__device__ float2 c_c32[17];
__device__ float2 c_lnc[11];
__device__ float2 c_ln2;
__device__ float2 c_eps;
__device__ double c_recip[NF + 1];   // 1.0/i

// ---------------------------- double-single ops ----------------------------
struct DS { float hi, lo; };
__device__ __forceinline__ DS two_sum(float a, float b) {
    float s = a + b, bb = s - a;
    float e = (a - (s - bb)) + (b - bb);
    return {s, e};
}
__device__ __forceinline__ DS quick2(float a, float b) {
    float s = a + b;
    return {s, b - (s - a)};
}
__device__ __forceinline__ DS ds_add(DS a, DS b) {
    DS s = two_sum(a.hi, b.hi);
    return quick2(s.hi, s.lo + a.lo + b.lo);
}
__device__ __forceinline__ DS ds_mul(DS a, DS b) {
    float p = a.hi * b.hi;
    float e = fmaf(a.hi, b.hi, -p);
    e = fmaf(a.hi, b.lo, e);
    e = fmaf(a.lo, b.hi, e);
    return quick2(p, e);
}
__device__ __forceinline__ DS ds_neg(DS a) { return {-a.hi, -a.lo}; }
__device__ __forceinline__ DS ds_from_d(double v) {
    float hi = (float)v;
    return {hi, (float)(v - (double)hi)};
}

// DS natural log; v > 0 well inside float range. abs err ~1e-13.
__device__ DS ds_log(DS v) {
    int e;
    float mh = frexpf(v.hi, &e);
    if (mh < 0.7071067811865476f) e -= 1;
    float sc = ldexpf(1.0f, -e);
    DS m = {v.hi * sc, v.lo * sc};
    DS num = ds_add(m, {-1.0f, 0.0f});
    DS den = ds_add(m, { 1.0f, 0.0f});
    float r = 1.0f / den.hi;
    float q1 = num.hi * r;
    DS t  = ds_add(num, ds_neg(ds_mul(den, {q1, 0.f})));
    float q2 = t.hi * r;
    DS t2 = ds_add(t,  ds_neg(ds_mul(den, {q2, 0.f})));
    float q3 = t2.hi * r;
    DS z = ds_add(ds_add({q1, 0.f}, {q2, 0.f}), {q3, 0.f});
    DS w = ds_mul(z, z);
    DS p = {c_lnc[10].x, c_lnc[10].y};
    #pragma unroll
    for (int k = 9; k >= 0; --k)
        p = ds_add(ds_mul(p, w), {c_lnc[k].x, c_lnc[k].y});
    DS lnm = ds_mul(ds_mul({2.0f, 0.f}, z), p);
    return ds_add(ds_mul({(float)e, 0.f}, {c_ln2.x, c_ln2.y}), lnm);
}

// numpy pairwise sum (float32), exact replication
__device__ float np_pairwise_sum(const float* a, int n) {
    if (n < 8) {
        float r = 0.0f;
        for (int i = 0; i < n; ++i) r += a[i];
        return r;
    } else if (n <= 128) {
        float r[8];
        #pragma unroll
        for (int j = 0; j < 8; ++j) r[j] = a[j];
        int i = 8;
        for (; i < n - (n % 8); i += 8) {
            #pragma unroll
            for (int j = 0; j < 8; ++j) r[j] += a[i + j];
        }
        float res = ((r[0] + r[1]) + (r[2] + r[3])) + ((r[4] + r[5]) + (r[6] + r[7]));
        for (; i < n; ++i) res += a[i];
        return res;
    } else {
        int n2 = n / 2;
        n2 -= n2 % 8;
        return np_pairwise_sum(a, n2) + np_pairwise_sum(a + n2, n - n2);
    }
}

// ------------------------------ 0) init ------------------------------------
__global__ void k_init() {
    int i = threadIdx.x;
    if (i < WIN) {
        double ang = -2.0 * PI_D * (double)i / 64.0;
        double sn, co;
        sincos(ang, &sn, &co);
        DS a = ds_from_d(co), b = ds_from_d(sn);
        c_tw_re[i] = make_float2(a.hi, a.lo);
        c_tw_im[i] = make_float2(b.hi, b.lo);
        DS wd = ds_from_d(0.5 - 0.5 * cos(2.0 * PI_D * (double)i / 63.0));
        c_win[i] = make_float2(wd.hi, wd.lo);
    }
    if (i <= 16) {
        DS c = ds_from_d(2.0 * cos(2.0 * PI_D * (double)i / 32.0));
        c_c32[i] = make_float2(c.hi, c.lo);
    }
    if (i <= 10) {
        DS c = ds_from_d(1.0 / (double)(2 * i + 1));
        c_lnc[i] = make_float2(c.hi, c.lo);
    }
    if (i == 0) {
        DS l2 = ds_from_d(0.69314718055994530941723212145818);
        c_ln2 = make_float2(l2.hi, l2.lo);
        DS ep = ds_from_d(1e-8);
        c_eps = make_float2(ep.hi, ep.lo);
    }
    if (i <= NF) c_recip[i] = i ? 1.0 / (double)i : 0.0;
}

// -------- 1) stage x -> g_x (HBM) + channel mean (float4 streaming) ---------
__global__ void k_sig(const float* __restrict__ x) {
    int t4 = blockIdx.x * blockDim.x + threadIdx.x;
    int b = blockIdx.y;
    if (t4 >= Ln / 4) return;
    const float4* p = (const float4*)(x + (size_t)b * Cn * Ln) + t4;
    float4 s = make_float4(0.f, 0.f, 0.f, 0.f);
    #pragma unroll
    for (int c = 0; c < Cn; ++c) {
        float4 v = p[(size_t)c * (Ln / 4)];
        ((float4*)g_x[b][c])[t4] = v;
        s.x += v.x; s.y += v.y; s.z += v.z; s.w += v.w;
    }
    s.x *= 0.03125f; s.y *= 0.03125f; s.z *= 0.03125f; s.w *= 0.03125f;
    ((float4*)g_sig[b])[t4] = s;
}

// ------------- 2) spectrogram features (DS fp32 DFT + DS log) --------------
__global__ void k_feats() {
    __shared__ float2 sv[WIN];
    __shared__ float2 twr[WIN], twi[WIN];
    __shared__ float  fr[WIN];
    __shared__ float  smean;
    int b = blockIdx.y, f = blockIdx.x, i = threadIdx.x;

    twr[i] = c_tw_re[i]; twi[i] = c_tw_im[i];
    fr[i] = g_sig[b][f * HOP + i];
    __syncthreads();

    if (i == 0) {
        float r[8];
        #pragma unroll
        for (int j = 0; j < 8; ++j) r[j] = fr[j];
        for (int o = 8; o < 64; o += 8) {
            #pragma unroll
            for (int j = 0; j < 8; ++j) r[j] += fr[o + j];
        }
        float s = ((r[0] + r[1]) + (r[2] + r[3])) + ((r[4] + r[5]) + (r[6] + r[7]));
        smean = s / 64.0f;
    }
    __syncthreads();

    {
        float d = fr[i] - smean;
        float2 w = c_win[i];
        float p = d * w.x;
        float e = fmaf(d, w.x, -p);
        e = fmaf(d, w.y, e);
        DS r = quick2(p, e);
        sv[i] = make_float2(r.hi, r.lo);
    }
    __syncthreads();

    if (i < ND) {
        DS re = {0.f, 0.f}, im = {0.f, 0.f};
        #pragma unroll 4
        for (int t = 0; t < WIN; ++t) {
            int m = (i * t) & 63;
            DS v  = {sv[t].x, sv[t].y};
            DS cr = {twr[m].x, twr[m].y};
            DS ci = {twi[m].x, twi[m].y};
            re = ds_add(re, ds_mul(v, cr));
            im = ds_add(im, ds_mul(v, ci));
        }
        DS p2 = ds_add(ds_mul(re, re), ds_mul(im, im));
        p2 = ds_add(p2, {c_eps.x, c_eps.y});
        DS lg = ds_log(p2);
        g_feats[b][f][i] = (double)lg.hi + (double)lg.lo;
    }
}

// ---------------- 3) prefix sums (fp64) + S2 totals --------------------------
__global__ void k_prefix() {
    int b = blockIdx.x, d = threadIdx.x;
    if (d < ND) {
        double a = 0.0, a2 = 0.0;
        g_cs[b][0][d] = 0.0; g_cs2[b][0][d] = 0.0;
        int t = 0;
        for (; t + 8 <= NF; t += 8) {
            double v[8];
            #pragma unroll
            for (int j = 0; j < 8; ++j) v[j] = g_feats[b][t + j][d];
            #pragma unroll
            for (int j = 0; j < 8; ++j) {
                a += v[j]; a2 += v[j] * v[j];
                g_cs[b][t + j + 1][d]  = a;
                g_cs2[b][t + j + 1][d] = a2;
            }
        }
        for (; t < NF; ++t) {
            double v = g_feats[b][t][d];
            a += v; a2 += v * v;
            g_cs[b][t + 1][d]  = a;
            g_cs2[b][t + 1][d] = a2;
        }
    }
    __syncthreads();
    for (int t = threadIdx.x; t <= NF; t += 64) {
        double s = 0.0;
        #pragma unroll
        for (int dd = 0; dd < ND; ++dd) s += g_cs2[b][t][dd];
        g_s2[b][t] = s;
    }
}

// ------ 4) PELT DP: warp/batch, 8 lanes per candidate, recip not divide -----
__global__ void k_pelt() {
    __shared__ double sFc[NF + 1];
    __shared__ double sVals[NF + 1];
    __shared__ short  sPrev[NF + 1];
    __shared__ short  sCands[NF + 2];

    int b = blockIdx.x, lane = threadIdx.x;   // 32 threads
    int cg = lane >> 3;   // candidate slot within pass (0..3)
    int dl = lane & 7;    // dim lane (0..7)
    if (lane == 0) { sFc[0] = -PEN; sCands[0] = 0; }
    int ncand = 1;
    __syncwarp();

    for (int t = 1; t <= NF; ++t) {
        const double* ct = g_cs[b][t];
        double S2t = g_s2[b][t];
        double ctd[5];
        #pragma unroll
        for (int q = 0; q < 5; ++q) {
            int d = dl + q * 8;
            ctd[q] = (d < ND) ? ct[d] : 0.0;
        }

        for (int base = 0; base < ncand; base += 4) {
            int j = base + cg;
            double acc = 0.0;
            int c = 0;
            bool act = (j < ncand);
            if (act) {
                c = sCands[j];
                const double* pc = g_cs[b][c];
                #pragma unroll
                for (int q = 0; q < 5; ++q) {
                    int d = dl + q * 8;
                    if (d < ND) {
                        double su = ctd[q] - pc[d];
                        acc = fma(su, su, acc);
                    }
                }
            }
            acc += __shfl_down_sync(0xffffffffu, acc, 4);
            acc += __shfl_down_sync(0xffffffffu, acc, 2);
            acc += __shfl_down_sync(0xffffffffu, acc, 1);
            if (act && dl == 0) {
                double cost = (S2t - g_s2[b][c]) - acc * c_recip[t - c];
                sVals[j] = sFc[c] + cost + PEN;
            }
        }
        __syncwarp();

        // argmin with first-index tiebreak (np.argmin semantics)
        double bv = 1e300; int bj = 1 << 30;
        for (int j = lane; j < ncand; j += 32) {
            double v = sVals[j];
            if (v < bv) { bv = v; bj = j; }
        }
        #pragma unroll
        for (int o = 16; o; o >>= 1) {
            double ov = __shfl_down_sync(0xffffffffu, bv, o);
            int    oj = __shfl_down_sync(0xffffffffu, bj, o);
            if (ov < bv || (ov == bv && oj < bj)) { bv = ov; bj = oj; }
        }
        bv = __shfl_sync(0xffffffffu, bv, 0);
        bj = __shfl_sync(0xffffffffu, bj, 0);
        if (lane == 0) { sFc[t] = bv; sPrev[t] = sCands[bj]; }
        __syncwarp();

        // prune: order-preserving ballot compaction
        double thr = bv + PEN;
        int newn = 0;
        for (int base = 0; base < ncand; base += 32) {
            int j = base + lane;
            short cj = 0; bool keep = false;
            if (j < ncand) { cj = sCands[j]; keep = (sVals[j] <= thr); }
            unsigned msk = __ballot_sync(0xffffffffu, keep);
            int pos = newn + __popc(msk & ((1u << lane) - 1u));
            __syncwarp();
            if (keep) sCands[pos] = cj;
            newn += __popc(msk);
            __syncwarp();
        }
        if (lane == 0) sCands[newn] = (short)t;
        ncand = newn + 1;
        __syncwarp();
    }

    if (lane == 0) {
        short bps[NF + 1];
        int nb = 0, t = NF;
        while (t > 0) { bps[nb++] = (short)t; t = sPrev[t]; }
        int bnd[MAXSEG];
        int bc = 1; bnd[0] = 0;
        for (int ii = nb - 1; ii >= 1; --ii) {
            int k = bps[ii];
            int bpos = (k < NF) ? HOP * k : Ln;
            if (bpos > Ln) bpos = Ln;
            if (bpos - bnd[bc - 1] >= 8 && bc < MAXSEG - 1) bnd[bc++] = bpos;
        }
        if (Ln - bnd[bc - 1] < 8 && bc > 1) bc--;
        bnd[bc++] = Ln;
        int nseg = bc - 1;
        int off = 0;
        for (int s = 0; s < nseg; ++s) {
            g_seg_s[b][s]   = bnd[s];
            g_seg_e[b][s]   = bnd[s + 1];
            g_seg_off[b][s] = off;
            off += (bnd[s + 1] - bnd[s]) >> 1;
        }
        g_nseg[b] = nseg;
    }
}

// ---- 5) fused: fp32 pairwise mean + DS-Goertzel + stats (warp/segment) -----
__global__ void k_segspec() {
    __shared__ float buf[4][SEGBUF];
    int b = blockIdx.y;
    int wid = threadIdx.x >> 5, lane = threadIdx.x & 31;
    int nseg = g_nseg[b];
    int wg = blockIdx.x * 4 + wid;
    int nwarp = gridDim.x * 4;
    float* wb = buf[wid];

    for (int seg = wg; seg < nseg; seg += nwarp) {
        int s = g_seg_s[b][seg], e = g_seg_e[b][seg];
        int n = e - s, nf = n >> 1;
        const float* sp = &g_sig[b][s];

        float mean = 0.0f;
        if (lane == 0) mean = __fdiv_rn(np_pairwise_sum(sp, n), (float)n);
        mean = __shfl_sync(0xffffffffu, mean, 0);

        bool small = (n <= SEGBUF);
        __syncwarp();
        if (small)
            for (int t = lane; t < n; t += 32) wb[t] = sp[t] - mean;
        __syncwarp();

        double pw[16];
        int nb = 0;
        double tot = 0.0, mv = -1.0; int mk = 1 << 30;

        for (int k = lane + 1; k <= nf; k += 32) {
            DS coeff;
            if (n == 32) { float2 cc = c_c32[k]; coeff = {cc.x, cc.y}; }
            else coeff = ds_from_d(2.0 * cos(2.0 * PI_D * (double)k / (double)n));

            DS s1 = {0.f, 0.f}, s2 = {0.f, 0.f};
            if (small) {
                for (int t = 0; t < n; ++t) {
                    DS t1 = ds_add({wb[t], 0.f}, ds_neg(s2));
                    DS sn = ds_add(t1, ds_mul(coeff, s1));
                    s2 = s1; s1 = sn;
                }
            } else {
                for (int t = 0; t < n; ++t) {
                    float v = sp[t] - mean;
                    DS t1 = ds_add({v, 0.f}, ds_neg(s2));
                    DS sn = ds_add(t1, ds_mul(coeff, s1));
                    s2 = s1; s1 = sn;
                }
            }
            DS aa = ds_mul(s1, s1);
            DS bb = ds_mul(s2, s2);
            DS cc = ds_mul(ds_mul(coeff, s1), s2);
            DS pp = ds_add(ds_add(aa, bb), ds_neg(cc));
            double pwv = (double)pp.hi + (double)pp.lo;
            if (pwv < 0.0) pwv = 0.0;
            if (small) pw[nb] = pwv;
            else g_spec[b][g_seg_off[b][seg] + (k - 1)] = pwv;
            ++nb;
            tot += pwv;
            if (pwv > mv) { mv = pwv; mk = k; }
        }
        __syncwarp();

        #pragma unroll
        for (int o = 16; o; o >>= 1) {
            tot += __shfl_down_sync(0xffffffffu, tot, o);
            double ov = __shfl_down_sync(0xffffffffu, mv, o);
            int    ok = __shfl_down_sync(0xffffffffu, mk, o);
            if (ov > mv || (ov == mv && ok < mk)) { mv = ov; mk = ok; }
        }
        tot = __shfl_sync(0xffffffffu, tot, 0);
        mk  = __shfl_sync(0xffffffffu, mk, 0);

        double dpv, bwvv;
        if (tot <= 0.0 || nf < 1) {
            dpv = (double)n; bwvv = 0.0;
        } else {
            double invtot = 1.0 / tot, invnf = 1.0 / (double)nf;
            double cacc = 0.0;
            { int i2 = 0;
              for (int k = lane + 1; k <= nf; k += 32) {
                  double v = small ? pw[i2++] : g_spec[b][g_seg_off[b][seg] + (k - 1)];
                  cacc += (v * invtot) * ((double)k * invnf);
              } }
            #pragma unroll
            for (int o = 16; o; o >>= 1) cacc += __shfl_down_sync(0xffffffffu, cacc, o);
            cacc = __shfl_sync(0xffffffffu, cacc, 0);

            double bacc = 0.0;
            { int i2 = 0;
              for (int k = lane + 1; k <= nf; k += 32) {
                  double v = small ? pw[i2++] : g_spec[b][g_seg_off[b][seg] + (k - 1)];
                  double fd = (double)k * invnf - cacc;
                  bacc += (v * invtot) * fd * fd;
              } }
            #pragma unroll
            for (int o = 16; o; o >>= 1) bacc += __shfl_down_sync(0xffffffffu, bacc, o);
            bacc = __shfl_sync(0xffffffffu, bacc, 0);

            dpv  = (double)n / (double)mk;
            bwvv = sqrt(bacc);
        }

        if (lane == 0) {
            g_dp[b][seg]  = dpv;
            g_bwv[b][seg] = bwvv;
            double raw = dpv / (1.0 + bwvv);
            double r = rint(raw * 0.5);
            int pl = (int)(2.0 * r);
            pl = pl < 8 ? 8 : (pl > 64 ? 64 : pl);
            g_pl[b][seg] = pl;
        }
        __syncwarp();
    }
}

// ------------------------- 6) token build (scan) ----------------------------
__global__ void k_tokens() {
    __shared__ int cnt[512];
    int b = blockIdx.x, tid = threadIdx.x;
    int nseg = g_nseg[b];
    int c = 0, s = 0, e = 0, pl = 8;
    if (tid < nseg) {
        s = g_seg_s[b][tid]; e = g_seg_e[b][tid]; pl = g_pl[b][tid];
        int len = e - s;
        int nfl = len / pl;
        c = nfl + ((len - nfl * pl) > 0 ? 1 : 0);
    }
    cnt[tid] = c;
    __syncthreads();
    for (int o = 1; o < 512; o <<= 1) {
        int v = cnt[tid];
        if (tid >= o) v += cnt[tid - o];
        __syncthreads();
        cnt[tid] = v;
        __syncthreads();
    }
    if (tid < nseg) {
        int off = cnt[tid] - c;
        int len = e - s;
        int nfl = len / pl;
        for (int i = 0; i < nfl; ++i) {
            g_tok_s[b][off + i]   = s + i * pl;
            g_tok_e[b][off + i]   = s + (i + 1) * pl;
            g_tok_seg[b][off + i] = tid;
        }
        if (nfl * pl < len) {
            g_tok_s[b][off + nfl]   = s + nfl * pl;
            g_tok_e[b][off + nfl]   = e;
            g_tok_seg[b][off + nfl] = tid;
        }
    }
    if (tid == 0) g_ntok[b] = cnt[511];
}

// -------------------------- 7a) scalar outputs ------------------------------
__global__ void k_scalars(float* __restrict__ o_mask, float* __restrict__ o_start,
                          float* __restrict__ o_end, float* __restrict__ o_center,
                          float* __restrict__ o_span, float* __restrict__ o_regime,
                          int mt) {
    int i = blockIdx.x * blockDim.x + threadIdx.x;
    int b = blockIdx.y;
    if (i >= mt) return;
    float m = 0.f, st = 0.f, en = 0.f, ce = 0.f, sp = 0.f, r0 = 0.f, r1 = 0.f, r2 = 0.f;
    if (i < g_ntok[b]) {
        int s = g_tok_s[b][i], e = g_tok_e[b][i], seg = g_tok_seg[b][i];
        m = 1.0f;
        st = (float)s; en = (float)e;
        ce = ((float)s + (float)e - 1.0f) * 0.5f / 16383.0f;
        sp = (float)(e - s) / 16384.0f;
        int sl = g_seg_e[b][seg] - g_seg_s[b][seg];
        r0 = (float)(g_dp[b][seg] / 16384.0);
        r1 = (float)g_bwv[b][seg];
        r2 = (float)((double)sl / 16384.0);
    }
    size_t idx = (size_t)b * mt + i;
    o_mask[idx] = m; o_start[idx] = st; o_end[idx] = en;
    o_center[idx] = ce; o_span[idx] = sp;
    o_regime[idx * 3 + 0] = r0;
    o_regime[idx * 3 + 1] = r1;
    o_regime[idx * 3 + 2] = r2;
}

__global__ void k_ntok(float* __restrict__ o_ntok) {
    int b = threadIdx.x;
    if (b < Bn) o_ntok[b] = (float)g_ntok[b];
}

// ---- 7b) patches (gather + lerp) g_x -> d_out, float4 stores ---------------
__global__ __launch_bounds__(256) void k_patches(float* __restrict__ o_patch, int mt) {
    int b = blockIdx.y;
    int tok = blockIdx.x * 2 + (threadIdx.x >> 7);
    int r = threadIdx.x & 127;
    int c = r >> 2, q = r & 3;
    if (tok >= mt) return;

    size_t obase = (((size_t)b * mt + tok) * Cn + c) * ANCH + q * 4;
    float4 v = make_float4(0.f, 0.f, 0.f, 0.f);
    if (tok < g_ntok[b]) {
        int s = g_tok_s[b][tok], e = g_tok_e[b][tok];
        int il = e - s;
        float scale = (float)il / 16.0f;
        const float* row = g_x[b][c] + s;
        float o[4];
        #pragma unroll
        for (int jj = 0; jj < 4; ++jj) {
            int j = q * 4 + jj;
            float coord = ((float)j + 0.5f) * scale - 0.5f;
            coord = fminf(fmaxf(coord, 0.0f), (float)(il - 1));
            int l = (int)floorf(coord);
            int h = min(l + 1, il - 1);
            float w = coord - (float)l;
            o[jj] = row[l] * (1.0f - w) + row[h] * w;
        }
        v = make_float4(o[0], o[1], o[2], o[3]);
    }
    *(float4*)(o_patch + obase) = v;
}

// --------------------------------- launch -----------------------------------
extern "C" void kernel_launch(void* const* d_in, const int* in_sizes, int n_in,
                              void* d_out, int out_size) {
    const float* x = (const float*)d_in[0];
    float* out = (float*)d_out;

    long long mt_ll = ((long long)out_size - Bn) / (16384 + 5 * Bn + 3 * Bn);
    if (mt_ll < 1) mt_ll = 1;
    int mt = (int)mt_ll;

    float* o_patch  = out;
    float* o_mask   = out + (size_t)Bn * mt * Cn * ANCH;
    float* o_start  = o_mask   + (size_t)Bn * mt;
    float* o_end    = o_start  + (size_t)Bn * mt;
    float* o_center = o_end    + (size_t)Bn * mt;
    float* o_span   = o_center + (size_t)Bn * mt;
    float* o_regime = o_span   + (size_t)Bn * mt;
    float* o_ntok   = o_regime + (size_t)Bn * mt * 3;

    k_init<<<1, 512>>>();
    k_sig<<<dim3(16, Bn), 256>>>(x);
    k_feats<<<dim3(NF, Bn), WIN>>>();
    k_prefix<<<Bn, 64>>>();
    k_pelt<<<Bn, 32>>>();
    k_segspec<<<dim3(128, Bn), 128>>>();
    k_tokens<<<Bn, 512>>>();
    k_scalars<<<dim3((mt + 255) / 256, Bn), 256>>>(o_mask, o_start, o_end,
                                                   o_center, o_span, o_regime, mt);
    k_ntok<<<1, Bn>>>(o_ntok);
    k_patches<<<dim3((mt + 1) / 2, Bn), 256>>>(o_patch, mt);
}

// round 11
// speedup vs baseline: 17.5287x; 1.4246x over previous
#include <cuda_runtime.h>
#include <math.h>

namespace {
constexpr int    Bn = 32, Cn = 32, Ln = 16384, WIN = 64, HOP = 32;
constexpr int    NF = 511, ND = 33;
constexpr double PEN = 5.0;
constexpr int    MAXSEG = 520, MAXTOK = 4608, ANCH = 16;
constexpr double PI_D = 3.14159265358979323846264338327950288;
constexpr int    SEGBUF = 1024;
// k_pelt dynamic smem layout (doubles): cs 16896 | s2 512 | Fc 512 | vals 512 | recip 512
constexpr int    PELT_DBL  = 16896 + 512 + 512 + 512 + 512;
constexpr size_t PELT_SMEM = PELT_DBL * 8 + (512 + 514) * 2 + 16;
}

// ------------------------------- scratch ----------------------------------
__device__ float  g_x[Bn][Cn][Ln];
__device__ float  g_sig[Bn][Ln];
__device__ double g_feats[Bn][NF][ND];
__device__ double g_cs [Bn][NF + 1][ND];
__device__ double g_cs2[Bn][NF + 1][ND];
__device__ double g_s2 [Bn][NF + 1];
__device__ int    g_nseg[Bn];
__device__ int    g_seg_s[Bn][MAXSEG];
__device__ int    g_seg_e[Bn][MAXSEG];
__device__ int    g_seg_off[Bn][MAXSEG];
__device__ double g_spec[Bn][Ln / 2 + 8];
__device__ double g_dp[Bn][MAXSEG];
__device__ double g_bwv[Bn][MAXSEG];
__device__ int    g_pl[Bn][MAXSEG];
__device__ int    g_ntok[Bn];
__device__ int    g_tok_s[Bn][MAXTOK];
__device__ int    g_tok_e[Bn][MAXTOK];
__device__ int    g_tok_seg[Bn][MAXTOK];

// precomputed constants
__device__ float2 c_tw_re[WIN], c_tw_im[WIN], c_win[WIN];
__device__ float2 c_c32[17];
__device__ float2 c_lnc[11];
__device__ float2 c_ln2;
__device__ float2 c_eps;
__device__ double c_recip[NF + 1];

// ---------------------------- double-single ops ----------------------------
struct DS { float hi, lo; };
__device__ __forceinline__ DS two_sum(float a, float b) {
    float s = a + b, bb = s - a;
    float e = (a - (s - bb)) + (b - bb);
    return {s, e};
}
__device__ __forceinline__ DS quick2(float a, float b) {
    float s = a + b;
    return {s, b - (s - a)};
}
__device__ __forceinline__ DS ds_add(DS a, DS b) {
    DS s = two_sum(a.hi, b.hi);
    return quick2(s.hi, s.lo + a.lo + b.lo);
}
__device__ __forceinline__ DS ds_mul(DS a, DS b) {
    float p = a.hi * b.hi;
    float e = fmaf(a.hi, b.hi, -p);
    e = fmaf(a.hi, b.lo, e);
    e = fmaf(a.lo, b.hi, e);
    return quick2(p, e);
}
__device__ __forceinline__ DS ds_neg(DS a) { return {-a.hi, -a.lo}; }
__device__ __forceinline__ DS ds_from_d(double v) {
    float hi = (float)v;
    return {hi, (float)(v - (double)hi)};
}

// DS natural log; v > 0 well inside float range. abs err ~1e-13.
__device__ DS ds_log(DS v) {
    int e;
    float mh = frexpf(v.hi, &e);
    if (mh < 0.7071067811865476f) e -= 1;
    float sc = ldexpf(1.0f, -e);
    DS m = {v.hi * sc, v.lo * sc};
    DS num = ds_add(m, {-1.0f, 0.0f});
    DS den = ds_add(m, { 1.0f, 0.0f});
    float r = 1.0f / den.hi;
    float q1 = num.hi * r;
    DS t  = ds_add(num, ds_neg(ds_mul(den, {q1, 0.f})));
    float q2 = t.hi * r;
    DS t2 = ds_add(t,  ds_neg(ds_mul(den, {q2, 0.f})));
    float q3 = t2.hi * r;
    DS z = ds_add(ds_add({q1, 0.f}, {q2, 0.f}), {q3, 0.f});
    DS w = ds_mul(z, z);
    DS p = {c_lnc[10].x, c_lnc[10].y};
    #pragma unroll
    for (int k = 9; k >= 0; --k)
        p = ds_add(ds_mul(p, w), {c_lnc[k].x, c_lnc[k].y});
    DS lnm = ds_mul(ds_mul({2.0f, 0.f}, z), p);
    return ds_add(ds_mul({(float)e, 0.f}, {c_ln2.x, c_ln2.y}), lnm);
}

// numpy pairwise sum (float32), exact replication
__device__ float np_pairwise_sum(const float* a, int n) {
    if (n < 8) {
        float r = 0.0f;
        for (int i = 0; i < n; ++i) r += a[i];
        return r;
    } else if (n <= 128) {
        float r[8];
        #pragma unroll
        for (int j = 0; j < 8; ++j) r[j] = a[j];
        int i = 8;
        for (; i < n - (n % 8); i += 8) {
            #pragma unroll
            for (int j = 0; j < 8; ++j) r[j] += a[i + j];
        }
        float res = ((r[0] + r[1]) + (r[2] + r[3])) + ((r[4] + r[5]) + (r[6] + r[7]));
        for (; i < n; ++i) res += a[i];
        return res;
    } else {
        int n2 = n / 2;
        n2 -= n2 % 8;
        return np_pairwise_sum(a, n2) + np_pairwise_sum(a + n2, n - n2);
    }
}

// ------------------------------ 0) init ------------------------------------
__global__ void k_init() {
    int i = threadIdx.x;
    if (i < WIN) {
        double ang = -2.0 * PI_D * (double)i / 64.0;
        double sn, co;
        sincos(ang, &sn, &co);
        DS a = ds_from_d(co), b = ds_from_d(sn);
        c_tw_re[i] = make_float2(a.hi, a.lo);
        c_tw_im[i] = make_float2(b.hi, b.lo);
        DS wd = ds_from_d(0.5 - 0.5 * cos(2.0 * PI_D * (double)i / 63.0));
        c_win[i] = make_float2(wd.hi, wd.lo);
    }
    if (i <= 16) {
        DS c = ds_from_d(2.0 * cos(2.0 * PI_D * (double)i / 32.0));
        c_c32[i] = make_float2(c.hi, c.lo);
    }
    if (i <= 10) {
        DS c = ds_from_d(1.0 / (double)(2 * i + 1));
        c_lnc[i] = make_float2(c.hi, c.lo);
    }
    if (i == 0) {
        DS l2 = ds_from_d(0.69314718055994530941723212145818);
        c_ln2 = make_float2(l2.hi, l2.lo);
        DS ep = ds_from_d(1e-8);
        c_eps = make_float2(ep.hi, ep.lo);
    }
    if (i <= NF) c_recip[i] = i ? 1.0 / (double)i : 0.0;
}

// -------- 1) stage x -> g_x (HBM) + channel mean (float4 streaming) ---------
__global__ void k_sig(const float* __restrict__ x) {
    int t4 = blockIdx.x * blockDim.x + threadIdx.x;
    int b = blockIdx.y;
    if (t4 >= Ln / 4) return;
    const float4* p = (const float4*)(x + (size_t)b * Cn * Ln) + t4;
    float4 s = make_float4(0.f, 0.f, 0.f, 0.f);
    #pragma unroll
    for (int c = 0; c < Cn; ++c) {
        float4 v = p[(size_t)c * (Ln / 4)];
        ((float4*)g_x[b][c])[t4] = v;
        s.x += v.x; s.y += v.y; s.z += v.z; s.w += v.w;
    }
    s.x *= 0.03125f; s.y *= 0.03125f; s.z *= 0.03125f; s.w *= 0.03125f;
    ((float4*)g_sig[b])[t4] = s;
}

// ------------- 2) spectrogram features (DS fp32 DFT + DS log) --------------
__global__ void k_feats() {
    __shared__ float2 sv[WIN];
    __shared__ float2 twr[WIN], twi[WIN];
    __shared__ float  fr[WIN];
    __shared__ float  smean;
    int b = blockIdx.y, f = blockIdx.x, i = threadIdx.x;

    twr[i] = c_tw_re[i]; twi[i] = c_tw_im[i];
    fr[i] = g_sig[b][f * HOP + i];
    __syncthreads();

    if (i == 0) {
        float r[8];
        #pragma unroll
        for (int j = 0; j < 8; ++j) r[j] = fr[j];
        for (int o = 8; o < 64; o += 8) {
            #pragma unroll
            for (int j = 0; j < 8; ++j) r[j] += fr[o + j];
        }
        float s = ((r[0] + r[1]) + (r[2] + r[3])) + ((r[4] + r[5]) + (r[6] + r[7]));
        smean = s / 64.0f;
    }
    __syncthreads();

    {
        float d = fr[i] - smean;
        float2 w = c_win[i];
        float p = d * w.x;
        float e = fmaf(d, w.x, -p);
        e = fmaf(d, w.y, e);
        DS r = quick2(p, e);
        sv[i] = make_float2(r.hi, r.lo);
    }
    __syncthreads();

    if (i < ND) {
        DS re = {0.f, 0.f}, im = {0.f, 0.f};
        #pragma unroll 4
        for (int t = 0; t < WIN; ++t) {
            int m = (i * t) & 63;
            DS v  = {sv[t].x, sv[t].y};
            DS cr = {twr[m].x, twr[m].y};
            DS ci = {twi[m].x, twi[m].y};
            re = ds_add(re, ds_mul(v, cr));
            im = ds_add(im, ds_mul(v, ci));
        }
        DS p2 = ds_add(ds_mul(re, re), ds_mul(im, im));
        p2 = ds_add(p2, {c_eps.x, c_eps.y});
        DS lg = ds_log(p2);
        g_feats[b][f][i] = (double)lg.hi + (double)lg.lo;
    }
}

// -------- 3a) prefix sums: warp-per-(d,b) Kogge-Stone scan with carry -------
__global__ void k_prefix() {
    int d = blockIdx.x, b = blockIdx.y, lane = threadIdx.x;
    double carry = 0.0, carry2 = 0.0;
    if (lane == 0) { g_cs[b][0][d] = 0.0; g_cs2[b][0][d] = 0.0; }
    for (int base = 0; base < NF; base += 32) {
        int t = base + lane;
        double v  = (t < NF) ? g_feats[b][t][d] : 0.0;
        double v2 = v * v;
        #pragma unroll
        for (int o = 1; o < 32; o <<= 1) {
            double n1 = __shfl_up_sync(0xffffffffu, v,  o);
            double n2 = __shfl_up_sync(0xffffffffu, v2, o);
            if (lane >= o) { v += n1; v2 += n2; }
        }
        v += carry; v2 += carry2;
        if (t < NF) {
            g_cs[b][t + 1][d]  = v;
            g_cs2[b][t + 1][d] = v2;
        }
        carry  = __shfl_sync(0xffffffffu, v, 31);
        carry2 = __shfl_sync(0xffffffffu, v2, 31);
    }
}

// -------- 3b) S2 totals: sum over d of cs2 ----------------------------------
__global__ void k_s2() {
    int b = blockIdx.x, t = threadIdx.x;
    double s = 0.0;
    #pragma unroll
    for (int dd = 0; dd < ND; ++dd) s += g_cs2[b][t][dd];
    g_s2[b][t] = s;
}

// ------ 4) PELT DP: warp/batch, full working set staged in shared memory ----
__global__ void k_pelt() {
    extern __shared__ double dyn[];
    double* s_cs    = dyn;                 // 16896 = 512*33
    double* s_s2    = dyn + 16896;         // 512
    double* s_Fc    = dyn + 17408;         // 512
    double* s_vals  = dyn + 17920;         // 512
    double* s_recip = dyn + 18432;         // 512
    short*  s_prev  = (short*)(dyn + 18944);        // 512 shorts
    short*  s_cands = s_prev + 512;                 // 514 shorts

    int b = blockIdx.x, tid = threadIdx.x;

    // stage: cs (135KB), s2, recip
    const double* gc = (const double*)g_cs[b];
    for (int i = tid; i < 16896; i += 256) s_cs[i] = gc[i];
    for (int i = tid; i < 512;   i += 256) {
        s_s2[i]    = g_s2[b][i];
        s_recip[i] = c_recip[i];
    }
    __syncthreads();
    if (tid >= 32) return;

    int lane = tid;
    int cg = lane >> 3;   // candidate slot within pass (0..3)
    int dl = lane & 7;    // dim lane (0..7)
    if (lane == 0) { s_Fc[0] = -PEN; s_cands[0] = 0; }
    int ncand = 1;
    __syncwarp();

    for (int t = 1; t <= NF; ++t) {
        const double* ct = s_cs + t * 33;
        double S2t = s_s2[t];
        double ctd[5];
        #pragma unroll
        for (int q = 0; q < 5; ++q) {
            int d = dl + q * 8;
            ctd[q] = (d < ND) ? ct[d] : 0.0;
        }

        if (ncand <= 4) {
            // ---------- register fast path ----------
            int j = cg;
            double val = 1e300;
            int c = 0;
            bool act = (j < ncand);
            if (act) c = s_cands[j];
            {
                const double* pc = s_cs + c * 33;
                double acc = 0.0;
                if (act) {
                    #pragma unroll
                    for (int q = 0; q < 5; ++q) {
                        int d = dl + q * 8;
                        if (d < ND) {
                            double su = ctd[q] - pc[d];
                            acc = fma(su, su, acc);
                        }
                    }
                }
                acc += __shfl_down_sync(0xffffffffu, acc, 4);
                acc += __shfl_down_sync(0xffffffffu, acc, 2);
                acc += __shfl_down_sync(0xffffffffu, acc, 1);
                if (act && dl == 0) {
                    double cost = (S2t - s_s2[c]) - acc * s_recip[t - c];
                    val = s_Fc[c] + cost + PEN;
                }
            }
            // gather vals of candidates 0..3 to every lane
            double v0 = __shfl_sync(0xffffffffu, val, 0);
            double v1 = __shfl_sync(0xffffffffu, val, 8);
            double v2 = __shfl_sync(0xffffffffu, val, 16);
            double v3 = __shfl_sync(0xffffffffu, val, 24);
            // argmin, first-index tiebreak (strict <)
            double bv = v0; int bj = 0;
            if (v1 < bv) { bv = v1; bj = 1; }
            if (v2 < bv) { bv = v2; bj = 2; }
            if (v3 < bv) { bv = v3; bj = 3; }
            if (lane == 0) { s_Fc[t] = bv; s_prev[t] = s_cands[bj]; }
            // prune
            double thr = bv + PEN;
            double vm = (lane == 0) ? v0 : (lane == 1) ? v1 : (lane == 2) ? v2 : v3;
            bool keep = (lane < ncand) && (vm <= thr);
            unsigned msk = __ballot_sync(0xffffffffu, keep);
            short cj = (lane < ncand) ? s_cands[lane] : (short)0;
            int pos = __popc(msk & ((1u << lane) - 1u));
            __syncwarp();
            if (keep) s_cands[pos] = cj;
            int newn = __popc(msk);
            if (lane == 0) s_cands[newn] = (short)t;
            ncand = newn + 1;
            __syncwarp();
        } else {
            // ---------- general smem path ----------
            for (int base = 0; base < ncand; base += 4) {
                int j = base + cg;
                double acc = 0.0;
                int c = 0;
                bool act = (j < ncand);
                if (act) {
                    c = s_cands[j];
                    const double* pc = s_cs + c * 33;
                    #pragma unroll
                    for (int q = 0; q < 5; ++q) {
                        int d = dl + q * 8;
                        if (d < ND) {
                            double su = ctd[q] - pc[d];
                            acc = fma(su, su, acc);
                        }
                    }
                }
                acc += __shfl_down_sync(0xffffffffu, acc, 4);
                acc += __shfl_down_sync(0xffffffffu, acc, 2);
                acc += __shfl_down_sync(0xffffffffu, acc, 1);
                if (act && dl == 0) {
                    double cost = (S2t - s_s2[c]) - acc * s_recip[t - c];
                    s_vals[j] = s_Fc[c] + cost + PEN;
                }
            }
            __syncwarp();

            double bv = 1e300; int bj = 1 << 30;
            for (int j = lane; j < ncand; j += 32) {
                double v = s_vals[j];
                if (v < bv) { bv = v; bj = j; }
            }
            #pragma unroll
            for (int o = 16; o; o >>= 1) {
                double ov = __shfl_down_sync(0xffffffffu, bv, o);
                int    oj = __shfl_down_sync(0xffffffffu, bj, o);
                if (ov < bv || (ov == bv && oj < bj)) { bv = ov; bj = oj; }
            }
            bv = __shfl_sync(0xffffffffu, bv, 0);
            bj = __shfl_sync(0xffffffffu, bj, 0);
            if (lane == 0) { s_Fc[t] = bv; s_prev[t] = s_cands[bj]; }
            __syncwarp();

            double thr = bv + PEN;
            int newn = 0;
            for (int base = 0; base < ncand; base += 32) {
                int j = base + lane;
                short cj = 0; bool keep = false;
                if (j < ncand) { cj = s_cands[j]; keep = (s_vals[j] <= thr); }
                unsigned msk = __ballot_sync(0xffffffffu, keep);
                int pos = newn + __popc(msk & ((1u << lane) - 1u));
                __syncwarp();
                if (keep) s_cands[pos] = cj;
                newn += __popc(msk);
                __syncwarp();
            }
            if (lane == 0) s_cands[newn] = (short)t;
            ncand = newn + 1;
            __syncwarp();
        }
    }

    if (lane == 0) {
        short bps[NF + 1];
        int nb = 0, t = NF;
        while (t > 0) { bps[nb++] = (short)t; t = s_prev[t]; }
        int bnd[MAXSEG];
        int bc = 1; bnd[0] = 0;
        for (int ii = nb - 1; ii >= 1; --ii) {
            int k = bps[ii];
            int bpos = (k < NF) ? HOP * k : Ln;
            if (bpos > Ln) bpos = Ln;
            if (bpos - bnd[bc - 1] >= 8 && bc < MAXSEG - 1) bnd[bc++] = bpos;
        }
        if (Ln - bnd[bc - 1] < 8 && bc > 1) bc--;
        bnd[bc++] = Ln;
        int nseg = bc - 1;
        int off = 0;
        for (int s = 0; s < nseg; ++s) {
            g_seg_s[b][s]   = bnd[s];
            g_seg_e[b][s]   = bnd[s + 1];
            g_seg_off[b][s] = off;
            off += (bnd[s + 1] - bnd[s]) >> 1;
        }
        g_nseg[b] = nseg;
    }
}

// ---- 5) fused: fp32 pairwise mean + DS-Goertzel + stats (warp/segment) -----
__global__ void k_segspec() {
    __shared__ float buf[4][SEGBUF];
    int b = blockIdx.y;
    int wid = threadIdx.x >> 5, lane = threadIdx.x & 31;
    int nseg = g_nseg[b];
    int wg = blockIdx.x * 4 + wid;
    int nwarp = gridDim.x * 4;
    float* wb = buf[wid];

    for (int seg = wg; seg < nseg; seg += nwarp) {
        int s = g_seg_s[b][seg], e = g_seg_e[b][seg];
        int n = e - s, nf = n >> 1;
        const float* sp = &g_sig[b][s];

        float mean = 0.0f;
        if (lane == 0) mean = __fdiv_rn(np_pairwise_sum(sp, n), (float)n);
        mean = __shfl_sync(0xffffffffu, mean, 0);

        bool small = (n <= SEGBUF);
        __syncwarp();
        if (small)
            for (int t = lane; t < n; t += 32) wb[t] = sp[t] - mean;
        __syncwarp();

        double pw[16];
        int nb = 0;
        double tot = 0.0, mv = -1.0; int mk = 1 << 30;

        for (int k = lane + 1; k <= nf; k += 32) {
            DS coeff;
            if (n == 32) { float2 cc = c_c32[k]; coeff = {cc.x, cc.y}; }
            else coeff = ds_from_d(2.0 * cos(2.0 * PI_D * (double)k / (double)n));

            DS s1 = {0.f, 0.f}, s2 = {0.f, 0.f};
            if (small) {
                for (int t = 0; t < n; ++t) {
                    DS t1 = ds_add({wb[t], 0.f}, ds_neg(s2));
                    DS sn = ds_add(t1, ds_mul(coeff, s1));
                    s2 = s1; s1 = sn;
                }
            } else {
                for (int t = 0; t < n; ++t) {
                    float v = sp[t] - mean;
                    DS t1 = ds_add({v, 0.f}, ds_neg(s2));
                    DS sn = ds_add(t1, ds_mul(coeff, s1));
                    s2 = s1; s1 = sn;
                }
            }
            DS aa = ds_mul(s1, s1);
            DS bb = ds_mul(s2, s2);
            DS cc = ds_mul(ds_mul(coeff, s1), s2);
            DS pp = ds_add(ds_add(aa, bb), ds_neg(cc));
            double pwv = (double)pp.hi + (double)pp.lo;
            if (pwv < 0.0) pwv = 0.0;
            if (small) pw[nb] = pwv;
            else g_spec[b][g_seg_off[b][seg] + (k - 1)] = pwv;
            ++nb;
            tot += pwv;
            if (pwv > mv) { mv = pwv; mk = k; }
        }
        __syncwarp();

        #pragma unroll
        for (int o = 16; o; o >>= 1) {
            tot += __shfl_down_sync(0xffffffffu, tot, o);
            double ov = __shfl_down_sync(0xffffffffu, mv, o);
            int    ok = __shfl_down_sync(0xffffffffu, mk, o);
            if (ov > mv || (ov == mv && ok < mk)) { mv = ov; mk = ok; }
        }
        tot = __shfl_sync(0xffffffffu, tot, 0);
        mk  = __shfl_sync(0xffffffffu, mk, 0);

        double dpv, bwvv;
        if (tot <= 0.0 || nf < 1) {
            dpv = (double)n; bwvv = 0.0;
        } else {
            double invtot = 1.0 / tot, invnf = 1.0 / (double)nf;
            double cacc = 0.0;
            { int i2 = 0;
              for (int k = lane + 1; k <= nf; k += 32) {
                  double v = small ? pw[i2++] : g_spec[b][g_seg_off[b][seg] + (k - 1)];
                  cacc += (v * invtot) * ((double)k * invnf);
              } }
            #pragma unroll
            for (int o = 16; o; o >>= 1) cacc += __shfl_down_sync(0xffffffffu, cacc, o);
            cacc = __shfl_sync(0xffffffffu, cacc, 0);

            double bacc = 0.0;
            { int i2 = 0;
              for (int k = lane + 1; k <= nf; k += 32) {
                  double v = small ? pw[i2++] : g_spec[b][g_seg_off[b][seg] + (k - 1)];
                  double fd = (double)k * invnf - cacc;
                  bacc += (v * invtot) * fd * fd;
              } }
            #pragma unroll
            for (int o = 16; o; o >>= 1) bacc += __shfl_down_sync(0xffffffffu, bacc, o);
            bacc = __shfl_sync(0xffffffffu, bacc, 0);

            dpv  = (double)n / (double)mk;
            bwvv = sqrt(bacc);
        }

        if (lane == 0) {
            g_dp[b][seg]  = dpv;
            g_bwv[b][seg] = bwvv;
            double raw = dpv / (1.0 + bwvv);
            double r = rint(raw * 0.5);
            int pl = (int)(2.0 * r);
            pl = pl < 8 ? 8 : (pl > 64 ? 64 : pl);
            g_pl[b][seg] = pl;
        }
        __syncwarp();
    }
}

// ------------------------- 6) token build (scan) ----------------------------
__global__ void k_tokens() {
    __shared__ int cnt[512];
    int b = blockIdx.x, tid = threadIdx.x;
    int nseg = g_nseg[b];
    int c = 0, s = 0, e = 0, pl = 8;
    if (tid < nseg) {
        s = g_seg_s[b][tid]; e = g_seg_e[b][tid]; pl = g_pl[b][tid];
        int len = e - s;
        int nfl = len / pl;
        c = nfl + ((len - nfl * pl) > 0 ? 1 : 0);
    }
    cnt[tid] = c;
    __syncthreads();
    for (int o = 1; o < 512; o <<= 1) {
        int v = cnt[tid];
        if (tid >= o) v += cnt[tid - o];
        __syncthreads();
        cnt[tid] = v;
        __syncthreads();
    }
    if (tid < nseg) {
        int off = cnt[tid] - c;
        int len = e - s;
        int nfl = len / pl;
        for (int i = 0; i < nfl; ++i) {
            g_tok_s[b][off + i]   = s + i * pl;
            g_tok_e[b][off + i]   = s + (i + 1) * pl;
            g_tok_seg[b][off + i] = tid;
        }
        if (nfl * pl < len) {
            g_tok_s[b][off + nfl]   = s + nfl * pl;
            g_tok_e[b][off + nfl]   = e;
            g_tok_seg[b][off + nfl] = tid;
        }
    }
    if (tid == 0) g_ntok[b] = cnt[511];
}

// -------------------------- 7a) scalar outputs ------------------------------
__global__ void k_scalars(float* __restrict__ o_mask, float* __restrict__ o_start,
                          float* __restrict__ o_end, float* __restrict__ o_center,
                          float* __restrict__ o_span, float* __restrict__ o_regime,
                          int mt) {
    int i = blockIdx.x * blockDim.x + threadIdx.x;
    int b = blockIdx.y;
    if (i >= mt) return;
    float m = 0.f, st = 0.f, en = 0.f, ce = 0.f, sp = 0.f, r0 = 0.f, r1 = 0.f, r2 = 0.f;
    if (i < g_ntok[b]) {
        int s = g_tok_s[b][i], e = g_tok_e[b][i], seg = g_tok_seg[b][i];
        m = 1.0f;
        st = (float)s; en = (float)e;
        ce = ((float)s + (float)e - 1.0f) * 0.5f / 16383.0f;
        sp = (float)(e - s) / 16384.0f;
        int sl = g_seg_e[b][seg] - g_seg_s[b][seg];
        r0 = (float)(g_dp[b][seg] / 16384.0);
        r1 = (float)g_bwv[b][seg];
        r2 = (float)((double)sl / 16384.0);
    }
    size_t idx = (size_t)b * mt + i;
    o_mask[idx] = m; o_start[idx] = st; o_end[idx] = en;
    o_center[idx] = ce; o_span[idx] = sp;
    o_regime[idx * 3 + 0] = r0;
    o_regime[idx * 3 + 1] = r1;
    o_regime[idx * 3 + 2] = r2;
}

__global__ void k_ntok(float* __restrict__ o_ntok) {
    int b = threadIdx.x;
    if (b < Bn) o_ntok[b] = (float)g_ntok[b];
}

// ---- 7b) patches (gather + lerp) g_x -> d_out, float4 stores ---------------
__global__ __launch_bounds__(256) void k_patches(float* __restrict__ o_patch, int mt) {
    int b = blockIdx.y;
    int tok = blockIdx.x * 2 + (threadIdx.x >> 7);
    int r = threadIdx.x & 127;
    int c = r >> 2, q = r & 3;
    if (tok >= mt) return;

    size_t obase = (((size_t)b * mt + tok) * Cn + c) * ANCH + q * 4;
    float4 v = make_float4(0.f, 0.f, 0.f, 0.f);
    if (tok < g_ntok[b]) {
        int s = g_tok_s[b][tok], e = g_tok_e[b][tok];
        int il = e - s;
        float scale = (float)il / 16.0f;
        const float* row = g_x[b][c] + s;
        float o[4];
        #pragma unroll
        for (int jj = 0; jj < 4; ++jj) {
            int j = q * 4 + jj;
            float coord = ((float)j + 0.5f) * scale - 0.5f;
            coord = fminf(fmaxf(coord, 0.0f), (float)(il - 1));
            int l = (int)floorf(coord);
            int h = min(l + 1, il - 1);
            float w = coord - (float)l;
            o[jj] = row[l] * (1.0f - w) + row[h] * w;
        }
        v = make_float4(o[0], o[1], o[2], o[3]);
    }
    *(float4*)(o_patch + obase) = v;
}

// --------------------------------- launch -----------------------------------
extern "C" void kernel_launch(void* const* d_in, const int* in_sizes, int n_in,
                              void* d_out, int out_size) {
    const float* x = (const float*)d_in[0];
    float* out = (float*)d_out;

    long long mt_ll = ((long long)out_size - Bn) / (16384 + 5 * Bn + 3 * Bn);
    if (mt_ll < 1) mt_ll = 1;
    int mt = (int)mt_ll;

    float* o_patch  = out;
    float* o_mask   = out + (size_t)Bn * mt * Cn * ANCH;
    float* o_start  = o_mask   + (size_t)Bn * mt;
    float* o_end    = o_start  + (size_t)Bn * mt;
    float* o_center = o_end    + (size_t)Bn * mt;
    float* o_span   = o_center + (size_t)Bn * mt;
    float* o_regime = o_span   + (size_t)Bn * mt;
    float* o_ntok   = o_regime + (size_t)Bn * mt * 3;

    static bool attr_done = false;
    if (!attr_done) {
        cudaFuncSetAttribute(k_pelt, cudaFuncAttributeMaxDynamicSharedMemorySize,
                             (int)PELT_SMEM);
        attr_done = true;
    }

    k_init<<<1, 512>>>();
    k_sig<<<dim3(16, Bn), 256>>>(x);
    k_feats<<<dim3(NF, Bn), WIN>>>();
    k_prefix<<<dim3(ND, Bn), 32>>>();
    k_s2<<<Bn, NF + 1>>>();
    k_pelt<<<Bn, 256, PELT_SMEM>>>();
    k_segspec<<<dim3(128, Bn), 128>>>();
    k_tokens<<<Bn, 512>>>();
    k_scalars<<<dim3((mt + 255) / 256, Bn), 256>>>(o_mask, o_start, o_end,
                                                   o_center, o_span, o_regime, mt);
    k_ntok<<<1, Bn>>>(o_ntok);
    k_patches<<<dim3((mt + 1) / 2, Bn), 256>>>(o_patch, mt);
}